// round 12
// baseline (speedup 1.0000x reference)
#include <cuda_runtime.h>
#include <cuda_bf16.h>
#include <stdint.h>
#include <math.h>

#define N_TOK 2048
#define HDIM  256
#define FFDIM 512
#define NLAYER 6
#define CAP   96

// programmatic dependent launch: allow dependents to launch ASAP, then wait on producers
#define GDC() do { \
    asm volatile("griddepcontrol.launch_dependents;"); \
    asm volatile("griddepcontrol.wait;" ::: "memory"); \
} while (0)

// ---------------- device scratch ----------------
__device__ float g_X  [N_TOK * HDIM];
__device__ float g_QKV[N_TOK * 3 * HDIM];
__device__ float g_T1 [N_TOK * HDIM];
__device__ float g_T2 [N_TOK * (HDIM/2)];
__device__ float g_eta[N_TOK];
__device__ float g_phi[N_TOK];
__device__ int   g_nbr[N_TOK * CAP];
__device__ int   g_cnt[N_TOK];

// packed bf16 activation planes: row = [hi(0..K-1) | lo(0..K-1)]
__device__ __nv_bfloat16 g_Aex [N_TOK * 512];    // K=256 sources (LN out / attn out / X)
__device__ __nv_bfloat16 g_FFex[N_TOK * 1024];   // K=512 (FF1 out)

// expanded bf16 weights (K' = 3K): planes [hi | hi | lo] along K'
__device__ __nv_bfloat16 g_WBqkv[NLAYER * 768 * 768];
__device__ __nv_bfloat16 g_WBo  [NLAYER * 256 * 768];
__device__ __nv_bfloat16 g_WB1  [NLAYER * 512 * 768];
__device__ __nv_bfloat16 g_WB2  [NLAYER * 256 * 1536];
__device__ __nv_bfloat16 g_WBhd [384 * 768];     // Wl1 (256 rows) ++ Wb1 (128 rows)
__device__ float         g_bhd  [384];           // bl1 ++ bb1

// ---------------- helpers ----------------
__device__ __forceinline__ unsigned su32(const void* p) {
    return (unsigned)__cvta_generic_to_shared(p);
}
__device__ __forceinline__ void bf16_split(float x, __nv_bfloat16& hi, __nv_bfloat16& lo) {
    hi = __float2bfloat16(x);
    lo = __float2bfloat16(x - __bfloat162float(hi));
}
__device__ __forceinline__ void mma_bf16(float c[4],
                                         unsigned a0, unsigned a1, unsigned a2, unsigned a3,
                                         unsigned b0, unsigned b1) {
    asm volatile(
        "mma.sync.aligned.m16n8k16.row.col.f32.bf16.bf16.f32 "
        "{%0,%1,%2,%3}, {%4,%5,%6,%7}, {%8,%9}, {%0,%1,%2,%3};\n"
        : "+f"(c[0]), "+f"(c[1]), "+f"(c[2]), "+f"(c[3])
        : "r"(a0), "r"(a1), "r"(a2), "r"(a3), "r"(b0), "r"(b1));
}
__device__ __forceinline__ void ldsm_x4(unsigned r[4], unsigned addr) {
    asm volatile("ldmatrix.sync.aligned.m8n8.x4.shared.b16 {%0,%1,%2,%3}, [%4];"
                 : "=r"(r[0]), "=r"(r[1]), "=r"(r[2]), "=r"(r[3]) : "r"(addr));
}
__device__ __forceinline__ void cpa16(unsigned saddr, const void* g) {
    asm volatile("cp.async.ca.shared.global [%0], [%1], 16;" :: "r"(saddr), "l"(g));
}
__device__ __forceinline__ void cpa_commit() {
    asm volatile("cp.async.commit_group;" ::: "memory");
}
template<int N> __device__ __forceinline__ void cpa_wait() {
    asm volatile("cp.async.wait_group %0;" :: "n"(N) : "memory");
}

// ---------------- merged weight expansion ----------------
__global__ void convw_all(const float* __restrict__ Wqkv, const float* __restrict__ Wo,
                          const float* __restrict__ W1,   const float* __restrict__ W2,
                          const float* __restrict__ Wl1,  const float* __restrict__ Wb1,
                          const float* __restrict__ bl1,  const float* __restrict__ bb1) {
    GDC();
    const long n0 = 6L * 768 * 256;
    const long n1 = n0 + 6L * 256 * 256;
    const long n2 = n1 + 6L * 512 * 256;
    const long n3 = n2 + 6L * 256 * 512;
    const long n4 = n3 + 256L * 256;
    const long n5 = n4 + 128L * 256;
    const long n6 = n5 + 384;
    for (long idx = (long)blockIdx.x * blockDim.x + threadIdx.x; idx < n6;
         idx += (long)gridDim.x * blockDim.x) {
        if (idx >= n5) {
            int i = (int)(idx - n5);
            g_bhd[i] = (i < 256) ? bl1[i] : bb1[i - 256];
            continue;
        }
        const float* src; __nv_bfloat16* dst; long loc; int K;
        if (idx < n0)      { src = Wqkv; dst = g_WBqkv; loc = idx;      K = 256; }
        else if (idx < n1) { src = Wo;   dst = g_WBo;   loc = idx - n0; K = 256; }
        else if (idx < n2) { src = W1;   dst = g_WB1;   loc = idx - n1; K = 256; }
        else if (idx < n3) { src = W2;   dst = g_WB2;   loc = idx - n2; K = 512; }
        else if (idx < n4) { src = Wl1;  dst = g_WBhd;  loc = idx - n3; K = 256; }
        else               { src = Wb1;  dst = g_WBhd + 256L * 768; loc = idx - n4; K = 256; }
        int k = (int)(loc % K);
        long t = loc / K;
        float x = src[loc];
        __nv_bfloat16 hi, lo;
        bf16_split(x, hi, lo);
        long base = t * (3L * K);
        dst[base + k]        = hi;     // plane 0: hi   (pairs A-hi)
        dst[base + K + k]    = hi;     // plane 1: hi   (pairs A-lo)
        dst[base + 2L*K + k] = lo;     // plane 2: lo   (pairs A-hi)
    }
}

// ---------------- embed ----------------
__global__ void embed_kernel(const float* __restrict__ xr,
                             const float* __restrict__ Win,
                             const float* __restrict__ b_in) {
    GDC();
    int n = blockIdx.x;
    int h = threadIdx.x;
    __shared__ float r[8];
    if (h < 8) r[h] = xr[n * 8 + h];
    __syncthreads();
    float acc = b_in[h];
#pragma unroll
    for (int k = 0; k < 8; k++) acc += r[k] * Win[h * 8 + k];
    g_X[n * HDIM + h] = acc;
    if (h == 0) {
        g_eta[n] = r[1] * 5.24f   - 2.62f;
        g_phi[n] = r[2] * 6.2832f - 3.1416f;
    }
}

// ---------------- neighbor list ----------------
__global__ void build_nbr_kernel() {
    GDC();
    int warp = (blockIdx.x * blockDim.x + threadIdx.x) >> 5;
    int lane = threadIdx.x & 31;
    if (warp >= N_TOK) return;
    int i = warp;
    float ei = g_eta[i], pi = g_phi[i];
    int c = 0;
    for (int j0 = 0; j0 < N_TOK; j0 += 32) {
        int j = j0 + lane;
        float de = ei - g_eta[j];
        float dp = pi - g_phi[j];
        dp = dp - 6.283185307179586f * rintf(dp * 0.15915494309189535f);
        float dr2 = de * de + dp * dp;
        bool keep = (dr2 <= 0.04f);
        unsigned m = __ballot_sync(0xffffffffu, keep);
        if (keep) {
            int pos = c + __popc(m & ((1u << lane) - 1u));
            if (pos < CAP) g_nbr[i * CAP + pos] = j;
        }
        c += __popc(m);
    }
    if (lane == 0) g_cnt[i] = (c < CAP) ? c : CAP;
}

// ---------------- LN -> packed planes (warp per row) ----------------
__global__ void ln_expand(const float* __restrict__ x,
                          const float* __restrict__ g,
                          const float* __restrict__ b) {
    GDC();
    int warp = (blockIdx.x * blockDim.x + threadIdx.x) >> 5;   // row
    int lane = threadIdx.x & 31;
    if (warp >= N_TOK) return;
    const float* row = x + (size_t)warp * 256 + lane * 8;
    float v[8];
    *(float4*)&v[0] = *(const float4*)&row[0];
    *(float4*)&v[4] = *(const float4*)&row[4];
    float s = 0.f, sq = 0.f;
#pragma unroll
    for (int j = 0; j < 8; j++) { s += v[j]; sq += v[j] * v[j]; }
#pragma unroll
    for (int off = 16; off; off >>= 1) {
        s  += __shfl_xor_sync(0xffffffffu, s,  off);
        sq += __shfl_xor_sync(0xffffffffu, sq, off);
    }
    float mean = s * (1.f / 256.f);
    float var  = sq * (1.f / 256.f) - mean * mean;
    float inv  = rsqrtf(var + 1e-5f);
    __nv_bfloat16 hi[8], lo[8];
#pragma unroll
    for (int j = 0; j < 8; j++) {
        float y = (v[j] - mean) * inv * g[lane * 8 + j] + b[lane * 8 + j];
        bf16_split(y, hi[j], lo[j]);
    }
    *(uint4*)&g_Aex[(size_t)warp * 512 + lane * 8]       = *(uint4*)hi;
    *(uint4*)&g_Aex[(size_t)warp * 512 + 256 + lane * 8] = *(uint4*)lo;
}

// ---------------- plain expand X -> planes ----------------
__global__ void expand_kernel(const float* __restrict__ src) {
    GDC();
    int n = blockIdx.x;
    int t = threadIdx.x;
    float y = src[n * 256 + t];
    __nv_bfloat16 hi, lo;
    bf16_split(y, hi, lo);
    g_Aex[(size_t)n * 512 + t]       = hi;
    g_Aex[(size_t)n * 512 + 256 + t] = lo;
}

// ---------------- streamed dual-buffer bf16 GEMM ----------------
// C[2048, Ncols] = Aplanes[2048, K] @ WBexp[Ncols, 3K]^T + bias
// A: packed plane rows [hi(K)|lo(K)] bf16, stride 2K. B: expanded, stride 3K.
// Tile 64x64, BK=64, 256 threads (8 warps 2x4; warp tile 32x16).
template<int KDIM, int RELU, int RES, int SPLIT, int EXPAND>
__global__ void __launch_bounds__(256)
fgemm(const __nv_bfloat16* __restrict__ Aex, const __nv_bfloat16* __restrict__ WB,
      const float* __restrict__ bias,
      float* __restrict__ out0, float* __restrict__ out1,
      __nv_bfloat16* __restrict__ Cexp, int Ncols) {
    constexpr int KP   = 3 * KDIM;
    constexpr int NCH  = KP / 64;
    constexpr int ASTR = 2 * KDIM;              // bf16 stride of A plane rows

    __shared__ __nv_bfloat16 sA[2][64][72];
    __shared__ __nv_bfloat16 sB[2][64][72];

    GDC();

    int tid  = threadIdx.x;
    int lane = tid & 31;
    int warp = tid >> 5;
    int wm = (warp & 1) * 32;
    int wn = (warp >> 1) * 16;
    int gq = lane >> 2;
    int tq = lane & 3;

    int m0 = blockIdx.y * 64;
    int n0 = blockIdx.x * 64;

    const uint4* Ag = (const uint4*)(Aex + (size_t)m0 * ASTR);
    const uint4* Bg = (const uint4*)(WB  + (size_t)n0 * KP);

    auto issue = [&](int ic, int st) {
        int kglob = ic * 64;
        int plane = kglob / KDIM;
        int k0    = kglob % KDIM;
        int acol8 = ((plane == 1) ? KDIM + k0 : k0) >> 3;
        int bcol8 = kglob >> 3;
#pragma unroll
        for (int v = 0; v < 2; v++) {
            int e = v * 256 + tid;
            int row = e >> 3, c8 = e & 7;
            cpa16(su32(&sA[st][row][c8 * 8]), Ag + (size_t)row * (ASTR >> 3) + acol8 + c8);
            cpa16(su32(&sB[st][row][c8 * 8]), Bg + (size_t)row * (KP >> 3)   + bcol8 + c8);
        }
        cpa_commit();
    };
    issue(0, 0);

    float acc[2][2][4];
#pragma unroll
    for (int mt = 0; mt < 2; mt++)
#pragma unroll
        for (int nt = 0; nt < 2; nt++)
#pragma unroll
            for (int r = 0; r < 4; r++) acc[mt][nt][r] = 0.f;

    int lr8 = lane & 7;
    int sel = lane >> 3;
    int aRow = (sel & 1) * 8 + lr8;
    int aCol = (sel >> 1) * 8;
    int bRow = lane & 15;
    int bCol = (lane >> 4) * 8;

    for (int ic = 0; ic < NCH; ic++) {
        if (ic + 1 < NCH) { issue(ic + 1, (ic + 1) & 1); cpa_wait<1>(); }
        else              { cpa_wait<0>(); }
        __syncthreads();
        int st = ic & 1;
#pragma unroll
        for (int kk = 0; kk < 4; kk++) {
            int kb = kk * 16;
            unsigned a[2][4], b[4];
            ldsm_x4(a[0], su32(&sA[st][wm + aRow][kb + aCol]));
            ldsm_x4(a[1], su32(&sA[st][wm + 16 + aRow][kb + aCol]));
            ldsm_x4(b,    su32(&sB[st][wn + bRow][kb + bCol]));
#pragma unroll
            for (int mt = 0; mt < 2; mt++) {
                mma_bf16(acc[mt][0], a[mt][0], a[mt][1], a[mt][2], a[mt][3], b[0], b[2]);
                mma_bf16(acc[mt][1], a[mt][0], a[mt][1], a[mt][2], a[mt][3], b[1], b[3]);
            }
        }
        __syncthreads();
    }

    // epilogue
#pragma unroll
    for (int mt = 0; mt < 2; mt++) {
#pragma unroll
        for (int half = 0; half < 2; half++) {
            int row = m0 + wm + mt * 16 + gq + half * 8;
#pragma unroll
            for (int nt = 0; nt < 2; nt++) {
                int col = n0 + wn + nt * 8 + 2 * tq;
                float v0 = acc[mt][nt][half * 2 + 0] + bias[col];
                float v1 = acc[mt][nt][half * 2 + 1] + bias[col + 1];
                if (RELU) { v0 = fmaxf(v0, 0.f); v1 = fmaxf(v1, 0.f); }
                if (RES) {
                    float2 old = *(float2*)&out0[(size_t)row * Ncols + col];
                    v0 += old.x; v1 += old.y;
                }
                if (EXPAND) {
                    __nv_bfloat16 h0, l0, h1, l1;
                    bf16_split(v0, h0, l0);
                    bf16_split(v1, h1, l1);
                    size_t base = (size_t)row * 2 * Ncols;
                    Cexp[base + col]             = h0;
                    Cexp[base + col + 1]         = h1;
                    Cexp[base + Ncols + col]     = l0;
                    Cexp[base + Ncols + col + 1] = l1;
                } else if (SPLIT) {
                    if (col < 256) *(float2*)&out0[(size_t)row * 256 + col] = make_float2(v0, v1);
                    else           *(float2*)&out1[(size_t)row * 128 + (col - 256)] = make_float2(v0, v1);
                } else {
                    *(float2*)&out0[(size_t)row * Ncols + col] = make_float2(v0, v1);
                }
            }
        }
    }
}

// ---------------- sparse attention: warp per (query, head); writes planes ----------------
__global__ void attn_kernel() {
    GDC();
    int warp = (blockIdx.x * blockDim.x + threadIdx.x) >> 5;
    int lane = threadIdx.x & 31;
    int n = warp >> 3;
    int h = warp & 7;
    if (n >= N_TOK) return;
    const float scale = 0.17677669529663687f;   // 1/sqrt(32)
    float q = g_QKV[n * 768 + h * 32 + lane];
    int c = g_cnt[n];
    float m = -1e30f, s = 0.f, o = 0.f;
    for (int t = 0; t < c; t++) {
        int j = g_nbr[n * CAP + t];
        float kv = g_QKV[j * 768 + 256 + h * 32 + lane];
        float prod = q * kv;
#pragma unroll
        for (int off = 16; off; off >>= 1) prod += __shfl_xor_sync(0xffffffffu, prod, off);
        float sc = prod * scale;
        float mn = fmaxf(m, sc);
        float corr = __expf(m - mn);
        float p = __expf(sc - mn);
        s = s * corr + p;
        float v = g_QKV[j * 768 + 512 + h * 32 + lane];
        o = o * corr + p * v;
        m = mn;
    }
    float y = o / s;
    __nv_bfloat16 hi, lo;
    bf16_split(y, hi, lo);
    int col = h * 32 + lane;
    g_Aex[(size_t)n * 512 + col]       = hi;
    g_Aex[(size_t)n * 512 + 256 + col] = lo;
}

// ---------------- finals: coords (24-col gemm) + beta head ----------------
__global__ void finals_kernel(const float* __restrict__ Wl2, const float* __restrict__ bl2,
                              const float* __restrict__ Wb2, const float* __restrict__ bb2,
                              float* __restrict__ out) {
    GDC();
    if (blockIdx.x < 192) {
        int idx = blockIdx.x * 256 + threadIdx.x;
        int row = idx / 24;
        int o   = idx % 24;
        const float* a = g_T1 + (size_t)row * 256;
        const float* w = Wl2 + (size_t)o * 256;
        float s = 0.f;
#pragma unroll 8
        for (int k = 0; k < 256; k++) s += a[k] * w[k];
        out[N_TOK + (size_t)row * 24 + o] = s + bl2[o];
    } else {
        int b2 = blockIdx.x - 192;
        int warp = b2 * 8 + (threadIdx.x >> 5);
        int lane = threadIdx.x & 31;
        if (warp >= N_TOK) return;
        float s = 0.f;
#pragma unroll
        for (int k = lane; k < 128; k += 32) s += g_T2[warp * 128 + k] * Wb2[k];
#pragma unroll
        for (int off = 16; off; off >>= 1) s += __shfl_xor_sync(0xffffffffu, s, off);
        if (lane == 0) {
            float z = s + bb2[0];
            float b = 1.f / (1.f + expf(-z));
            b = fminf(fmaxf(b, 1e-6f), 1.f - 1e-6f);
            out[warp] = b;
        }
    }
}

// ---------------- host: PDL launch helper ----------------
static cudaLaunchAttribute g_pdl_attr[1];

template<typename F, typename... Args>
static inline void pdl_launch(F f, dim3 grid, dim3 block, Args... args) {
    cudaLaunchConfig_t cfg = {};
    cfg.gridDim = grid;
    cfg.blockDim = block;
    cfg.dynamicSmemBytes = 0;
    cfg.stream = 0;
    g_pdl_attr[0].id = cudaLaunchAttributeProgrammaticStreamSerialization;
    g_pdl_attr[0].val.programmaticStreamSerializationAllowed = 1;
    cfg.attrs = g_pdl_attr;
    cfg.numAttrs = 1;
    cudaLaunchKernelEx(&cfg, f, args...);
}

extern "C" void kernel_launch(void* const* d_in, const int* in_sizes, int n_in,
                              void* d_out, int out_size) {
    const float* x_raw = (const float*)d_in[0];
    const float* Win  = (const float*)d_in[2];
    const float* b_in = (const float*)d_in[3];
    const float* Wqkv = (const float*)d_in[4];
    const float* bqkv = (const float*)d_in[5];
    const float* Wo   = (const float*)d_in[6];
    const float* bo   = (const float*)d_in[7];
    const float* W1   = (const float*)d_in[8];
    const float* b1   = (const float*)d_in[9];
    const float* W2   = (const float*)d_in[10];
    const float* b2   = (const float*)d_in[11];
    const float* g1   = (const float*)d_in[12];
    const float* be1  = (const float*)d_in[13];
    const float* g2   = (const float*)d_in[14];
    const float* be2  = (const float*)d_in[15];
    const float* Wl1  = (const float*)d_in[16];
    const float* bl1  = (const float*)d_in[17];
    const float* Wl2  = (const float*)d_in[18];
    const float* bl2  = (const float*)d_in[19];
    const float* Wb1  = (const float*)d_in[20];
    const float* bb1  = (const float*)d_in[21];
    const float* Wb2  = (const float*)d_in[22];
    const float* bb2  = (const float*)d_in[23];
    float* out = (float*)d_out;

    float *pX, *pQKV, *pT1, *pT2, *pbhd;
    cudaGetSymbolAddress((void**)&pX,   g_X);
    cudaGetSymbolAddress((void**)&pQKV, g_QKV);
    cudaGetSymbolAddress((void**)&pT1,  g_T1);
    cudaGetSymbolAddress((void**)&pT2,  g_T2);
    cudaGetSymbolAddress((void**)&pbhd, g_bhd);
    __nv_bfloat16 *pAex, *pFFex, *pWBqkv, *pWBo, *pWB1, *pWB2, *pWBhd;
    cudaGetSymbolAddress((void**)&pAex,   g_Aex);
    cudaGetSymbolAddress((void**)&pFFex,  g_FFex);
    cudaGetSymbolAddress((void**)&pWBqkv, g_WBqkv);
    cudaGetSymbolAddress((void**)&pWBo,   g_WBo);
    cudaGetSymbolAddress((void**)&pWB1,   g_WB1);
    cudaGetSymbolAddress((void**)&pWB2,   g_WB2);
    cudaGetSymbolAddress((void**)&pWBhd,  g_WBhd);

    pdl_launch(convw_all, dim3(2048), dim3(256),
               Wqkv, Wo, W1, W2, Wl1, Wb1, bl1, bb1);
    pdl_launch(embed_kernel, dim3(N_TOK), dim3(HDIM), x_raw, Win, b_in);
    pdl_launch(build_nbr_kernel, dim3(N_TOK / 8), dim3(256));

    for (int l = 0; l < NLAYER; l++) {
        const __nv_bfloat16* WBqkv_l = pWBqkv + (size_t)l * 768 * 768;
        const __nv_bfloat16* WBo_l   = pWBo   + (size_t)l * 256 * 768;
        const __nv_bfloat16* WB1_l   = pWB1   + (size_t)l * 512 * 768;
        const __nv_bfloat16* WB2_l   = pWB2   + (size_t)l * 256 * 1536;

        pdl_launch(ln_expand, dim3(N_TOK / 8), dim3(256),
                   (const float*)pX, g1 + l * 256, be1 + l * 256);
        pdl_launch(fgemm<256,0,0,0,0>, dim3(12, 32), dim3(256),
                   (const __nv_bfloat16*)pAex, (const __nv_bfloat16*)WBqkv_l,
                   bqkv + l * 768, pQKV, (float*)nullptr, (__nv_bfloat16*)nullptr, 768);
        pdl_launch(attn_kernel, dim3((N_TOK * 8 * 32) / 256), dim3(256));
        pdl_launch(fgemm<256,0,1,0,0>, dim3(4, 32), dim3(256),
                   (const __nv_bfloat16*)pAex, (const __nv_bfloat16*)WBo_l,
                   bo + l * 256, pX, (float*)nullptr, (__nv_bfloat16*)nullptr, 256);
        pdl_launch(ln_expand, dim3(N_TOK / 8), dim3(256),
                   (const float*)pX, g2 + l * 256, be2 + l * 256);
        pdl_launch(fgemm<256,1,0,0,1>, dim3(8, 32), dim3(256),
                   (const __nv_bfloat16*)pAex, (const __nv_bfloat16*)WB1_l,
                   b1 + l * 512, (float*)nullptr, (float*)nullptr, pFFex, 512);
        pdl_launch(fgemm<512,0,1,0,0>, dim3(4, 32), dim3(256),
                   (const __nv_bfloat16*)pFFex, (const __nv_bfloat16*)WB2_l,
                   b2 + l * 256, pX, (float*)nullptr, (__nv_bfloat16*)nullptr, 256);
    }

    // heads
    pdl_launch(expand_kernel, dim3(N_TOK), dim3(HDIM), (const float*)pX);
    pdl_launch(fgemm<256,1,0,1,0>, dim3(6, 32), dim3(256),
               (const __nv_bfloat16*)pAex, (const __nv_bfloat16*)pWBhd,
               (const float*)pbhd, pT1, pT2, (__nv_bfloat16*)nullptr, 384);
    pdl_launch(finals_kernel, dim3(448), dim3(256), Wl2, bl2, Wb2, bb2, out);
}

// round 13
// speedup vs baseline: 1.4218x; 1.4218x over previous
#include <cuda_runtime.h>
#include <cuda_bf16.h>
#include <stdint.h>
#include <math.h>

#define N_TOK 2048
#define HDIM  256
#define FFDIM 512
#define NLAYER 6
#define CAP   96

// ---------------- device scratch ----------------
__device__ float g_X  [N_TOK * HDIM];
__device__ float g_QKV[N_TOK * 3 * HDIM];
__device__ float g_T1 [N_TOK * HDIM];
__device__ float g_T2 [N_TOK * (HDIM/2)];
__device__ float g_eta[N_TOK];
__device__ float g_phi[N_TOK];
__device__ int   g_nbr[N_TOK * CAP];
__device__ int   g_cnt[N_TOK];

// packed bf16 activation planes: row = [hi(0..K-1) | lo(0..K-1)]
__device__ __nv_bfloat16 g_Aex [N_TOK * 512];    // K=256 sources (LN out / attn out / X)
__device__ __nv_bfloat16 g_FFex[N_TOK * 1024];   // K=512 (FF1 out)

// expanded bf16 weights (K' = 3K): planes [hi | hi | lo] along K'
__device__ __nv_bfloat16 g_WBqkv[NLAYER * 768 * 768];
__device__ __nv_bfloat16 g_WBo  [NLAYER * 256 * 768];
__device__ __nv_bfloat16 g_WB1  [NLAYER * 512 * 768];
__device__ __nv_bfloat16 g_WB2  [NLAYER * 256 * 1536];
__device__ __nv_bfloat16 g_WBhd [384 * 768];     // Wl1 (256 rows) ++ Wb1 (128 rows)
__device__ float         g_bhd  [384];           // bl1 ++ bb1

// ---------------- helpers ----------------
__device__ __forceinline__ unsigned su32(const void* p) {
    return (unsigned)__cvta_generic_to_shared(p);
}
__device__ __forceinline__ void bf16_split(float x, __nv_bfloat16& hi, __nv_bfloat16& lo) {
    hi = __float2bfloat16(x);
    lo = __float2bfloat16(x - __bfloat162float(hi));
}
__device__ __forceinline__ void mma_bf16(float c[4],
                                         unsigned a0, unsigned a1, unsigned a2, unsigned a3,
                                         unsigned b0, unsigned b1) {
    asm volatile(
        "mma.sync.aligned.m16n8k16.row.col.f32.bf16.bf16.f32 "
        "{%0,%1,%2,%3}, {%4,%5,%6,%7}, {%8,%9}, {%0,%1,%2,%3};\n"
        : "+f"(c[0]), "+f"(c[1]), "+f"(c[2]), "+f"(c[3])
        : "r"(a0), "r"(a1), "r"(a2), "r"(a3), "r"(b0), "r"(b1));
}
__device__ __forceinline__ void ldsm_x4(unsigned r[4], unsigned addr) {
    asm volatile("ldmatrix.sync.aligned.m8n8.x4.shared.b16 {%0,%1,%2,%3}, [%4];"
                 : "=r"(r[0]), "=r"(r[1]), "=r"(r[2]), "=r"(r[3]) : "r"(addr));
}
__device__ __forceinline__ void cpa16(unsigned saddr, const void* g) {
    asm volatile("cp.async.ca.shared.global [%0], [%1], 16;" :: "r"(saddr), "l"(g));
}
__device__ __forceinline__ void cpa_commit() {
    asm volatile("cp.async.commit_group;" ::: "memory");
}
template<int N> __device__ __forceinline__ void cpa_wait() {
    asm volatile("cp.async.wait_group %0;" :: "n"(N) : "memory");
}

// ---------------- merged weight expansion ----------------
__global__ void convw_all(const float* __restrict__ Wqkv, const float* __restrict__ Wo,
                          const float* __restrict__ W1,   const float* __restrict__ W2,
                          const float* __restrict__ Wl1,  const float* __restrict__ Wb1,
                          const float* __restrict__ bl1,  const float* __restrict__ bb1) {
    const long n0 = 6L * 768 * 256;
    const long n1 = n0 + 6L * 256 * 256;
    const long n2 = n1 + 6L * 512 * 256;
    const long n3 = n2 + 6L * 256 * 512;
    const long n4 = n3 + 256L * 256;
    const long n5 = n4 + 128L * 256;
    const long n6 = n5 + 384;
    for (long idx = (long)blockIdx.x * blockDim.x + threadIdx.x; idx < n6;
         idx += (long)gridDim.x * blockDim.x) {
        if (idx >= n5) {
            int i = (int)(idx - n5);
            g_bhd[i] = (i < 256) ? bl1[i] : bb1[i - 256];
            continue;
        }
        const float* src; __nv_bfloat16* dst; long loc; int K;
        if (idx < n0)      { src = Wqkv; dst = g_WBqkv; loc = idx;      K = 256; }
        else if (idx < n1) { src = Wo;   dst = g_WBo;   loc = idx - n0; K = 256; }
        else if (idx < n2) { src = W1;   dst = g_WB1;   loc = idx - n1; K = 256; }
        else if (idx < n3) { src = W2;   dst = g_WB2;   loc = idx - n2; K = 512; }
        else if (idx < n4) { src = Wl1;  dst = g_WBhd;  loc = idx - n3; K = 256; }
        else               { src = Wb1;  dst = g_WBhd + 256L * 768; loc = idx - n4; K = 256; }
        int k = (int)(loc % K);
        long t = loc / K;
        float x = src[loc];
        __nv_bfloat16 hi, lo;
        bf16_split(x, hi, lo);
        long base = t * (3L * K);
        dst[base + k]        = hi;     // plane 0: hi   (pairs A-hi)
        dst[base + K + k]    = hi;     // plane 1: hi   (pairs A-lo)
        dst[base + 2L*K + k] = lo;     // plane 2: lo   (pairs A-hi)
    }
}

// ---------------- embed + LN1(layer0) + plane write ----------------
__global__ void embed_ln(const float* __restrict__ xr,
                         const float* __restrict__ Win,
                         const float* __restrict__ b_in,
                         const float* __restrict__ g,
                         const float* __restrict__ b) {
    int n = blockIdx.x;
    int h = threadIdx.x;               // 256
    __shared__ float r[8];
    __shared__ float r1[8], r2[8];
    if (h < 8) r[h] = xr[n * 8 + h];
    __syncthreads();
    float acc = b_in[h];
#pragma unroll
    for (int k = 0; k < 8; k++) acc += r[k] * Win[h * 8 + k];
    g_X[n * HDIM + h] = acc;
    if (h == 0) {
        g_eta[n] = r[1] * 5.24f   - 2.62f;
        g_phi[n] = r[2] * 6.2832f - 3.1416f;
    }
    // LayerNorm over the block
    float s = acc;
#pragma unroll
    for (int off = 16; off; off >>= 1) s += __shfl_xor_sync(0xffffffffu, s, off);
    if ((h & 31) == 0) r1[h >> 5] = s;
    __syncthreads();
    float tot = 0.f;
#pragma unroll
    for (int w = 0; w < 8; w++) tot += r1[w];
    float mean = tot * (1.f / 256.f);
    float d = acc - mean;
    float s2 = d * d;
#pragma unroll
    for (int off = 16; off; off >>= 1) s2 += __shfl_xor_sync(0xffffffffu, s2, off);
    if ((h & 31) == 0) r2[h >> 5] = s2;
    __syncthreads();
    float vtot = 0.f;
#pragma unroll
    for (int w = 0; w < 8; w++) vtot += r2[w];
    float var = vtot * (1.f / 256.f);
    float y = d * rsqrtf(var + 1e-5f) * g[h] + b[h];
    __nv_bfloat16 hi, lo;
    bf16_split(y, hi, lo);
    g_Aex[(size_t)n * 512 + h]       = hi;
    g_Aex[(size_t)n * 512 + 256 + h] = lo;
}

// ---------------- neighbor list ----------------
__global__ void build_nbr_kernel() {
    int warp = (blockIdx.x * blockDim.x + threadIdx.x) >> 5;
    int lane = threadIdx.x & 31;
    if (warp >= N_TOK) return;
    int i = warp;
    float ei = g_eta[i], pi = g_phi[i];
    int c = 0;
    for (int j0 = 0; j0 < N_TOK; j0 += 32) {
        int j = j0 + lane;
        float de = ei - g_eta[j];
        float dp = pi - g_phi[j];
        dp = dp - 6.283185307179586f * rintf(dp * 0.15915494309189535f);
        float dr2 = de * de + dp * dp;
        bool keep = (dr2 <= 0.04f);
        unsigned m = __ballot_sync(0xffffffffu, keep);
        if (keep) {
            int pos = c + __popc(m & ((1u << lane) - 1u));
            if (pos < CAP) g_nbr[i * CAP + pos] = j;
        }
        c += __popc(m);
    }
    if (lane == 0) g_cnt[i] = (c < CAP) ? c : CAP;
}

// ---------------- streamed dual-buffer bf16 GEMM (as R11) ----------------
// C[2048, Ncols] = Aplanes[2048, K] @ WBexp[Ncols, 3K]^T + bias
// Tile 64x64, BK=64, 256 threads (8 warps 2x4; warp tile 32x16).
template<int KDIM, int RELU, int RES, int SPLIT, int EXPAND>
__global__ void __launch_bounds__(256)
fgemm(const __nv_bfloat16* __restrict__ Aex, const __nv_bfloat16* __restrict__ WB,
      const float* __restrict__ bias,
      float* __restrict__ out0, float* __restrict__ out1,
      __nv_bfloat16* __restrict__ Cexp, int Ncols) {
    constexpr int KP   = 3 * KDIM;
    constexpr int NCH  = KP / 64;
    constexpr int ASTR = 2 * KDIM;

    __shared__ __nv_bfloat16 sA[2][64][72];
    __shared__ __nv_bfloat16 sB[2][64][72];

    int tid  = threadIdx.x;
    int lane = tid & 31;
    int warp = tid >> 5;
    int wm = (warp & 1) * 32;
    int wn = (warp >> 1) * 16;
    int gq = lane >> 2;
    int tq = lane & 3;

    int m0 = blockIdx.y * 64;
    int n0 = blockIdx.x * 64;

    const uint4* Ag = (const uint4*)(Aex + (size_t)m0 * ASTR);
    const uint4* Bg = (const uint4*)(WB  + (size_t)n0 * KP);

    auto issue = [&](int ic, int st) {
        int kglob = ic * 64;
        int plane = kglob / KDIM;
        int k0    = kglob % KDIM;
        int acol8 = ((plane == 1) ? KDIM + k0 : k0) >> 3;
        int bcol8 = kglob >> 3;
#pragma unroll
        for (int v = 0; v < 2; v++) {
            int e = v * 256 + tid;
            int row = e >> 3, c8 = e & 7;
            cpa16(su32(&sA[st][row][c8 * 8]), Ag + (size_t)row * (ASTR >> 3) + acol8 + c8);
            cpa16(su32(&sB[st][row][c8 * 8]), Bg + (size_t)row * (KP >> 3)   + bcol8 + c8);
        }
        cpa_commit();
    };
    issue(0, 0);

    float acc[2][2][4];
#pragma unroll
    for (int mt = 0; mt < 2; mt++)
#pragma unroll
        for (int nt = 0; nt < 2; nt++)
#pragma unroll
            for (int r = 0; r < 4; r++) acc[mt][nt][r] = 0.f;

    int lr8 = lane & 7;
    int sel = lane >> 3;
    int aRow = (sel & 1) * 8 + lr8;
    int aCol = (sel >> 1) * 8;
    int bRow = lane & 15;
    int bCol = (lane >> 4) * 8;

    for (int ic = 0; ic < NCH; ic++) {
        if (ic + 1 < NCH) { issue(ic + 1, (ic + 1) & 1); cpa_wait<1>(); }
        else              { cpa_wait<0>(); }
        __syncthreads();
        int st = ic & 1;
#pragma unroll
        for (int kk = 0; kk < 4; kk++) {
            int kb = kk * 16;
            unsigned a[2][4], b[4];
            ldsm_x4(a[0], su32(&sA[st][wm + aRow][kb + aCol]));
            ldsm_x4(a[1], su32(&sA[st][wm + 16 + aRow][kb + aCol]));
            ldsm_x4(b,    su32(&sB[st][wn + bRow][kb + bCol]));
#pragma unroll
            for (int mt = 0; mt < 2; mt++) {
                mma_bf16(acc[mt][0], a[mt][0], a[mt][1], a[mt][2], a[mt][3], b[0], b[2]);
                mma_bf16(acc[mt][1], a[mt][0], a[mt][1], a[mt][2], a[mt][3], b[1], b[3]);
            }
        }
        __syncthreads();
    }

#pragma unroll
    for (int mt = 0; mt < 2; mt++) {
#pragma unroll
        for (int half = 0; half < 2; half++) {
            int row = m0 + wm + mt * 16 + gq + half * 8;
#pragma unroll
            for (int nt = 0; nt < 2; nt++) {
                int col = n0 + wn + nt * 8 + 2 * tq;
                float v0 = acc[mt][nt][half * 2 + 0] + bias[col];
                float v1 = acc[mt][nt][half * 2 + 1] + bias[col + 1];
                if (RELU) { v0 = fmaxf(v0, 0.f); v1 = fmaxf(v1, 0.f); }
                if (RES) {
                    float2 old = *(float2*)&out0[(size_t)row * Ncols + col];
                    v0 += old.x; v1 += old.y;
                }
                if (EXPAND) {
                    __nv_bfloat16 h0, l0, h1, l1;
                    bf16_split(v0, h0, l0);
                    bf16_split(v1, h1, l1);
                    size_t base = (size_t)row * 2 * Ncols;
                    Cexp[base + col]             = h0;
                    Cexp[base + col + 1]         = h1;
                    Cexp[base + Ncols + col]     = l0;
                    Cexp[base + Ncols + col + 1] = l1;
                } else if (SPLIT) {
                    if (col < 256) *(float2*)&out0[(size_t)row * 256 + col] = make_float2(v0, v1);
                    else           *(float2*)&out1[(size_t)row * 128 + (col - 256)] = make_float2(v0, v1);
                } else {
                    *(float2*)&out0[(size_t)row * Ncols + col] = make_float2(v0, v1);
                }
            }
        }
    }
}

// ---------------- fused residual-GEMM + LayerNorm(+expand) ----------------
// X[rows] += Aplanes @ WB^T + bias  (N = 256 full width per CTA, M-tile = 16)
// then per-row: DO_LN ? LayerNorm(X)*g+b : X  -> bf16 hi/lo planes into g_Aex.
// Grid: 128 CTAs. 256 threads, 8 warps; warp w covers cols [w*32, w*32+32).
template<int KDIM, int DO_LN>
__global__ void __launch_bounds__(256)
fgemm_ln(const __nv_bfloat16* __restrict__ Aex, const __nv_bfloat16* __restrict__ WB,
         const float* __restrict__ bias,
         const float* __restrict__ gam, const float* __restrict__ bet) {
    constexpr int KP   = 3 * KDIM;
    constexpr int NCH  = KP / 32;               // BK = 32
    constexpr int ASTR = 2 * KDIM;
    constexpr int RSTR = 40;                    // smem row stride (bf16) for 32-col chunks

    __shared__ __nv_bfloat16 sbuf[2][272 * RSTR];   // per stage: A rows 0..15, B rows 16..271

    int tid  = threadIdx.x;
    int lane = tid & 31;
    int warp = tid >> 5;
    int gq = lane >> 2;
    int tq = lane & 3;
    int m0 = blockIdx.x * 16;

    auto issue = [&](int ic, int st) {
        int kglob = ic * 32;
        int plane = kglob / KDIM;
        int k0    = kglob % KDIM;
        int aoff  = (plane == 1) ? KDIM + k0 : k0;
        __nv_bfloat16* sA = &sbuf[st][0];
        __nv_bfloat16* sB = &sbuf[st][16 * RSTR];
        if (tid < 64) {
            int row = tid >> 2, c = tid & 3;
            cpa16(su32(sA + row * RSTR + c * 8),
                  Aex + (size_t)(m0 + row) * ASTR + aoff + c * 8);
        }
#pragma unroll
        for (int v = 0; v < 4; v++) {
            int seg = v * 256 + tid;
            int row = seg >> 2, c = seg & 3;
            cpa16(su32(sB + row * RSTR + c * 8),
                  WB + (size_t)row * KP + kglob + c * 8);
        }
        cpa_commit();
    };
    issue(0, 0);

    float acc[4][4];
#pragma unroll
    for (int nt = 0; nt < 4; nt++)
#pragma unroll
        for (int r = 0; r < 4; r++) acc[nt][r] = 0.f;

    int lr8 = lane & 7;
    int sel = lane >> 3;
    int aRow = (sel & 1) * 8 + lr8;
    int aCol = (sel >> 1) * 8;
    int bRow = lane & 15;
    int bCol = (lane >> 4) * 8;
    int wcol = warp * 32;

    for (int ic = 0; ic < NCH; ic++) {
        if (ic + 1 < NCH) { issue(ic + 1, (ic + 1) & 1); cpa_wait<1>(); }
        else              { cpa_wait<0>(); }
        __syncthreads();
        int st = ic & 1;
        __nv_bfloat16* sA = &sbuf[st][0];
        __nv_bfloat16* sB = &sbuf[st][16 * RSTR];
#pragma unroll
        for (int kk = 0; kk < 2; kk++) {
            int kb = kk * 16;
            unsigned a[4], bA[4], bB[4];
            ldsm_x4(a,  su32(sA + aRow * RSTR + kb + aCol));
            ldsm_x4(bA, su32(sB + (wcol + bRow) * RSTR + kb + bCol));
            ldsm_x4(bB, su32(sB + (wcol + 16 + bRow) * RSTR + kb + bCol));
            mma_bf16(acc[0], a[0], a[1], a[2], a[3], bA[0], bA[2]);
            mma_bf16(acc[1], a[0], a[1], a[2], a[3], bA[1], bA[3]);
            mma_bf16(acc[2], a[0], a[1], a[2], a[3], bB[0], bB[2]);
            mma_bf16(acc[3], a[0], a[1], a[2], a[3], bB[1], bB[3]);
        }
        __syncthreads();
    }

    // epilogue: scatter acc + bias + residual into Cbuf (aliases stage 0)
    float* Cbuf = (float*)&sbuf[0][0];          // 16 x 256 fp32 = 16KB
#pragma unroll
    for (int nt = 0; nt < 4; nt++) {
        int col = wcol + nt * 8 + 2 * tq;
        float v00 = acc[nt][0] + bias[col]     + g_X[(size_t)(m0 + gq) * 256 + col];
        float v01 = acc[nt][1] + bias[col + 1] + g_X[(size_t)(m0 + gq) * 256 + col + 1];
        float v10 = acc[nt][2] + bias[col]     + g_X[(size_t)(m0 + gq + 8) * 256 + col];
        float v11 = acc[nt][3] + bias[col + 1] + g_X[(size_t)(m0 + gq + 8) * 256 + col + 1];
        Cbuf[gq * 256 + col]           = v00;
        Cbuf[gq * 256 + col + 1]       = v01;
        Cbuf[(gq + 8) * 256 + col]     = v10;
        Cbuf[(gq + 8) * 256 + col + 1] = v11;
    }
    __syncthreads();

    // LN (or identity) per row: warp w handles rows 2w, 2w+1
#pragma unroll
    for (int rr = 0; rr < 2; rr++) {
        int r = warp * 2 + rr;
        int gr = m0 + r;
        float v[8];
        *(float4*)&v[0] = *(float4*)&Cbuf[r * 256 + lane * 8];
        *(float4*)&v[4] = *(float4*)&Cbuf[r * 256 + lane * 8 + 4];
        // write residual stream
        *(float4*)&g_X[(size_t)gr * 256 + lane * 8]     = *(float4*)&v[0];
        *(float4*)&g_X[(size_t)gr * 256 + lane * 8 + 4] = *(float4*)&v[4];
        float y[8];
        if (DO_LN) {
            float s = 0.f, sq = 0.f;
#pragma unroll
            for (int j = 0; j < 8; j++) { s += v[j]; sq += v[j] * v[j]; }
#pragma unroll
            for (int off = 16; off; off >>= 1) {
                s  += __shfl_xor_sync(0xffffffffu, s,  off);
                sq += __shfl_xor_sync(0xffffffffu, sq, off);
            }
            float mean = s * (1.f / 256.f);
            float var  = sq * (1.f / 256.f) - mean * mean;
            float inv  = rsqrtf(var + 1e-5f);
#pragma unroll
            for (int j = 0; j < 8; j++)
                y[j] = (v[j] - mean) * inv * gam[lane * 8 + j] + bet[lane * 8 + j];
        } else {
#pragma unroll
            for (int j = 0; j < 8; j++) y[j] = v[j];
        }
        __nv_bfloat16 hi[8], lo[8];
#pragma unroll
        for (int j = 0; j < 8; j++) bf16_split(y[j], hi[j], lo[j]);
        *(uint4*)&g_Aex[(size_t)gr * 512 + lane * 8]       = *(uint4*)hi;
        *(uint4*)&g_Aex[(size_t)gr * 512 + 256 + lane * 8] = *(uint4*)lo;
    }
}

// ---------------- sparse attention: warp per (query, head); writes planes ----------------
__global__ void attn_kernel() {
    int warp = (blockIdx.x * blockDim.x + threadIdx.x) >> 5;
    int lane = threadIdx.x & 31;
    int n = warp >> 3;
    int h = warp & 7;
    if (n >= N_TOK) return;
    const float scale = 0.17677669529663687f;   // 1/sqrt(32)
    float q = g_QKV[n * 768 + h * 32 + lane];
    int c = g_cnt[n];
    float m = -1e30f, s = 0.f, o = 0.f;
    for (int t = 0; t < c; t++) {
        int j = g_nbr[n * CAP + t];
        float kv = g_QKV[j * 768 + 256 + h * 32 + lane];
        float prod = q * kv;
#pragma unroll
        for (int off = 16; off; off >>= 1) prod += __shfl_xor_sync(0xffffffffu, prod, off);
        float sc = prod * scale;
        float mn = fmaxf(m, sc);
        float corr = __expf(m - mn);
        float p = __expf(sc - mn);
        s = s * corr + p;
        float v = g_QKV[j * 768 + 512 + h * 32 + lane];
        o = o * corr + p * v;
        m = mn;
    }
    float y = o / s;
    __nv_bfloat16 hi, lo;
    bf16_split(y, hi, lo);
    int col = h * 32 + lane;
    g_Aex[(size_t)n * 512 + col]       = hi;
    g_Aex[(size_t)n * 512 + 256 + col] = lo;
}

// ---------------- finals: coords (24-col gemm) + beta head ----------------
__global__ void finals_kernel(const float* __restrict__ Wl2, const float* __restrict__ bl2,
                              const float* __restrict__ Wb2, const float* __restrict__ bb2,
                              float* __restrict__ out) {
    if (blockIdx.x < 192) {
        int idx = blockIdx.x * 256 + threadIdx.x;
        int row = idx / 24;
        int o   = idx % 24;
        const float* a = g_T1 + (size_t)row * 256;
        const float* w = Wl2 + (size_t)o * 256;
        float s = 0.f;
#pragma unroll 8
        for (int k = 0; k < 256; k++) s += a[k] * w[k];
        out[N_TOK + (size_t)row * 24 + o] = s + bl2[o];
    } else {
        int b2 = blockIdx.x - 192;
        int warp = b2 * 8 + (threadIdx.x >> 5);
        int lane = threadIdx.x & 31;
        if (warp >= N_TOK) return;
        float s = 0.f;
#pragma unroll
        for (int k = lane; k < 128; k += 32) s += g_T2[warp * 128 + k] * Wb2[k];
#pragma unroll
        for (int off = 16; off; off >>= 1) s += __shfl_xor_sync(0xffffffffu, s, off);
        if (lane == 0) {
            float z = s + bb2[0];
            float b = 1.f / (1.f + expf(-z));
            b = fminf(fmaxf(b, 1e-6f), 1.f - 1e-6f);
            out[warp] = b;
        }
    }
}

extern "C" void kernel_launch(void* const* d_in, const int* in_sizes, int n_in,
                              void* d_out, int out_size) {
    const float* x_raw = (const float*)d_in[0];
    const float* Win  = (const float*)d_in[2];
    const float* b_in = (const float*)d_in[3];
    const float* Wqkv = (const float*)d_in[4];
    const float* bqkv = (const float*)d_in[5];
    const float* Wo   = (const float*)d_in[6];
    const float* bo   = (const float*)d_in[7];
    const float* W1   = (const float*)d_in[8];
    const float* b1   = (const float*)d_in[9];
    const float* W2   = (const float*)d_in[10];
    const float* b2   = (const float*)d_in[11];
    const float* g1   = (const float*)d_in[12];
    const float* be1  = (const float*)d_in[13];
    const float* g2   = (const float*)d_in[14];
    const float* be2  = (const float*)d_in[15];
    const float* Wl1  = (const float*)d_in[16];
    const float* bl1  = (const float*)d_in[17];
    const float* Wl2  = (const float*)d_in[18];
    const float* bl2  = (const float*)d_in[19];
    const float* Wb1  = (const float*)d_in[20];
    const float* bb1  = (const float*)d_in[21];
    const float* Wb2  = (const float*)d_in[22];
    const float* bb2  = (const float*)d_in[23];
    float* out = (float*)d_out;

    float *pX, *pQKV, *pT1, *pT2, *pbhd;
    cudaGetSymbolAddress((void**)&pX,   g_X);
    cudaGetSymbolAddress((void**)&pQKV, g_QKV);
    cudaGetSymbolAddress((void**)&pT1,  g_T1);
    cudaGetSymbolAddress((void**)&pT2,  g_T2);
    cudaGetSymbolAddress((void**)&pbhd, g_bhd);
    __nv_bfloat16 *pAex, *pFFex, *pWBqkv, *pWBo, *pWB1, *pWB2, *pWBhd;
    cudaGetSymbolAddress((void**)&pAex,   g_Aex);
    cudaGetSymbolAddress((void**)&pFFex,  g_FFex);
    cudaGetSymbolAddress((void**)&pWBqkv, g_WBqkv);
    cudaGetSymbolAddress((void**)&pWBo,   g_WBo);
    cudaGetSymbolAddress((void**)&pWB1,   g_WB1);
    cudaGetSymbolAddress((void**)&pWB2,   g_WB2);
    cudaGetSymbolAddress((void**)&pWBhd,  g_WBhd);

    convw_all<<<2048, 256>>>(Wqkv, Wo, W1, W2, Wl1, Wb1, bl1, bb1);
    embed_ln<<<N_TOK, HDIM>>>(x_raw, Win, b_in, g1, be1);   // layer-0 LN1 fused
    build_nbr_kernel<<<N_TOK / 8, 256>>>();

    for (int l = 0; l < NLAYER; l++) {
        const __nv_bfloat16* WBqkv_l = pWBqkv + (size_t)l * 768 * 768;
        const __nv_bfloat16* WBo_l   = pWBo   + (size_t)l * 256 * 768;
        const __nv_bfloat16* WB1_l   = pWB1   + (size_t)l * 512 * 768;
        const __nv_bfloat16* WB2_l   = pWB2   + (size_t)l * 256 * 1536;

        // QKV = LN1planes @ Wqkv^T + bqkv
        fgemm<256,0,0,0,0><<<dim3(12, 32), 256>>>(
            pAex, WBqkv_l, bqkv + l * 768, pQKV, nullptr, nullptr, 768);
        attn_kernel<<<(N_TOK * 8 * 32) / 256, 256>>>();
        // X += attn @ Wo^T + bo ; then LN2 -> planes
        fgemm_ln<256,1><<<128, 256>>>(
            pAex, WBo_l, bo + l * 256, g2 + l * 256, be2 + l * 256);
        // FF = relu(LN2planes @ W1^T + b1) -> FFex planes
        fgemm<256,1,0,0,1><<<dim3(8, 32), 256>>>(
            pAex, WB1_l, b1 + l * 512, nullptr, nullptr, pFFex, 512);
        // X += FF @ W2^T + b2 ; then LN1(next layer) or identity -> planes
        if (l < NLAYER - 1) {
            fgemm_ln<512,1><<<128, 256>>>(
                pFFex, WB2_l, b2 + l * 256, g1 + (l + 1) * 256, be1 + (l + 1) * 256);
        } else {
            fgemm_ln<512,0><<<128, 256>>>(
                pFFex, WB2_l, b2 + l * 256, nullptr, nullptr);
        }
    }

    // heads: [T1 | T2] = relu(Xplanes @ [Wl1;Wb1]^T + [bl1;bb1])
    fgemm<256,1,0,1,0><<<dim3(6, 32), 256>>>(
        pAex, pWBhd, pbhd, pT1, pT2, nullptr, 384);
    finals_kernel<<<448, 256>>>(Wl2, bl2, Wb2, bb2, out);
}

// round 14
// speedup vs baseline: 2.8270x; 1.9884x over previous
#include <cuda_runtime.h>
#include <cuda_bf16.h>
#include <stdint.h>
#include <math.h>

#define N_TOK 2048
#define HDIM  256
#define FFDIM 512
#define NLAYER 6
#define CAP   96

// ---------------- device scratch ----------------
__device__ float g_X  [N_TOK * HDIM];
__device__ float g_QKV[N_TOK * 3 * HDIM];
__device__ float g_T1 [N_TOK * HDIM];
__device__ float g_T2 [N_TOK * (HDIM/2)];
__device__ float g_eta[N_TOK];
__device__ float g_phi[N_TOK];
__device__ int   g_nbr[N_TOK * CAP];
__device__ int   g_cnt[N_TOK];

// packed bf16 activation planes: row = [hi(0..K-1) | lo(0..K-1)]
__device__ __nv_bfloat16 g_Aex [N_TOK * 512];    // K=256 sources (LN out / attn out / X)
__device__ __nv_bfloat16 g_FFex[N_TOK * 1024];   // K=512 (FF1 out)

// expanded bf16 weights (K' = 3K): planes [hi | hi | lo] along K'
__device__ __nv_bfloat16 g_WBqkv[NLAYER * 768 * 768];
__device__ __nv_bfloat16 g_WBo  [NLAYER * 256 * 768];
__device__ __nv_bfloat16 g_WB1  [NLAYER * 512 * 768];
__device__ __nv_bfloat16 g_WB2  [NLAYER * 256 * 1536];
__device__ __nv_bfloat16 g_WBhd [384 * 768];     // Wl1 (256 rows) ++ Wb1 (128 rows)
__device__ float         g_bhd  [384];           // bl1 ++ bb1

// ---------------- helpers ----------------
__device__ __forceinline__ unsigned su32(const void* p) {
    return (unsigned)__cvta_generic_to_shared(p);
}
__device__ __forceinline__ void bf16_split(float x, __nv_bfloat16& hi, __nv_bfloat16& lo) {
    hi = __float2bfloat16(x);
    lo = __float2bfloat16(x - __bfloat162float(hi));
}
__device__ __forceinline__ void mma_bf16(float c[4],
                                         unsigned a0, unsigned a1, unsigned a2, unsigned a3,
                                         unsigned b0, unsigned b1) {
    asm volatile(
        "mma.sync.aligned.m16n8k16.row.col.f32.bf16.bf16.f32 "
        "{%0,%1,%2,%3}, {%4,%5,%6,%7}, {%8,%9}, {%0,%1,%2,%3};\n"
        : "+f"(c[0]), "+f"(c[1]), "+f"(c[2]), "+f"(c[3])
        : "r"(a0), "r"(a1), "r"(a2), "r"(a3), "r"(b0), "r"(b1));
}
__device__ __forceinline__ void ldsm_x4(unsigned r[4], unsigned addr) {
    asm volatile("ldmatrix.sync.aligned.m8n8.x4.shared.b16 {%0,%1,%2,%3}, [%4];"
                 : "=r"(r[0]), "=r"(r[1]), "=r"(r[2]), "=r"(r[3]) : "r"(addr));
}
__device__ __forceinline__ void cpa16(unsigned saddr, const void* g) {
    asm volatile("cp.async.ca.shared.global [%0], [%1], 16;" :: "r"(saddr), "l"(g));
}
__device__ __forceinline__ void cpa_commit() {
    asm volatile("cp.async.commit_group;" ::: "memory");
}
template<int N> __device__ __forceinline__ void cpa_wait() {
    asm volatile("cp.async.wait_group %0;" :: "n"(N) : "memory");
}

// ---------------- merged weight expansion ----------------
__global__ void convw_all(const float* __restrict__ Wqkv, const float* __restrict__ Wo,
                          const float* __restrict__ W1,   const float* __restrict__ W2,
                          const float* __restrict__ Wl1,  const float* __restrict__ Wb1,
                          const float* __restrict__ bl1,  const float* __restrict__ bb1) {
    const long n0 = 6L * 768 * 256;
    const long n1 = n0 + 6L * 256 * 256;
    const long n2 = n1 + 6L * 512 * 256;
    const long n3 = n2 + 6L * 256 * 512;
    const long n4 = n3 + 256L * 256;
    const long n5 = n4 + 128L * 256;
    const long n6 = n5 + 384;
    for (long idx = (long)blockIdx.x * blockDim.x + threadIdx.x; idx < n6;
         idx += (long)gridDim.x * blockDim.x) {
        if (idx >= n5) {
            int i = (int)(idx - n5);
            g_bhd[i] = (i < 256) ? bl1[i] : bb1[i - 256];
            continue;
        }
        const float* src; __nv_bfloat16* dst; long loc; int K;
        if (idx < n0)      { src = Wqkv; dst = g_WBqkv; loc = idx;      K = 256; }
        else if (idx < n1) { src = Wo;   dst = g_WBo;   loc = idx - n0; K = 256; }
        else if (idx < n2) { src = W1;   dst = g_WB1;   loc = idx - n1; K = 256; }
        else if (idx < n3) { src = W2;   dst = g_WB2;   loc = idx - n2; K = 512; }
        else if (idx < n4) { src = Wl1;  dst = g_WBhd;  loc = idx - n3; K = 256; }
        else               { src = Wb1;  dst = g_WBhd + 256L * 768; loc = idx - n4; K = 256; }
        int k = (int)(loc % K);
        long t = loc / K;
        float x = src[loc];
        __nv_bfloat16 hi, lo;
        bf16_split(x, hi, lo);
        long base = t * (3L * K);
        dst[base + k]        = hi;     // plane 0: hi   (pairs A-hi)
        dst[base + K + k]    = hi;     // plane 1: hi   (pairs A-lo)
        dst[base + 2L*K + k] = lo;     // plane 2: lo   (pairs A-hi)
    }
}

// ---------------- embed ----------------
__global__ void embed_kernel(const float* __restrict__ xr,
                             const float* __restrict__ Win,
                             const float* __restrict__ b_in) {
    int n = blockIdx.x;
    int h = threadIdx.x;
    __shared__ float r[8];
    if (h < 8) r[h] = xr[n * 8 + h];
    __syncthreads();
    float acc = b_in[h];
#pragma unroll
    for (int k = 0; k < 8; k++) acc += r[k] * Win[h * 8 + k];
    g_X[n * HDIM + h] = acc;
    if (h == 0) {
        g_eta[n] = r[1] * 5.24f   - 2.62f;
        g_phi[n] = r[2] * 6.2832f - 3.1416f;
    }
}

// ---------------- neighbor list ----------------
__global__ void build_nbr_kernel() {
    int warp = (blockIdx.x * blockDim.x + threadIdx.x) >> 5;
    int lane = threadIdx.x & 31;
    if (warp >= N_TOK) return;
    int i = warp;
    float ei = g_eta[i], pi = g_phi[i];
    int c = 0;
    for (int j0 = 0; j0 < N_TOK; j0 += 32) {
        int j = j0 + lane;
        float de = ei - g_eta[j];
        float dp = pi - g_phi[j];
        dp = dp - 6.283185307179586f * rintf(dp * 0.15915494309189535f);
        float dr2 = de * de + dp * dp;
        bool keep = (dr2 <= 0.04f);
        unsigned m = __ballot_sync(0xffffffffu, keep);
        if (keep) {
            int pos = c + __popc(m & ((1u << lane) - 1u));
            if (pos < CAP) g_nbr[i * CAP + pos] = j;
        }
        c += __popc(m);
    }
    if (lane == 0) g_cnt[i] = (c < CAP) ? c : CAP;
}

// ---------------- LN -> packed planes (warp per row) ----------------
__global__ void ln_expand(const float* __restrict__ x,
                          const float* __restrict__ g,
                          const float* __restrict__ b) {
    int warp = (blockIdx.x * blockDim.x + threadIdx.x) >> 5;   // row
    int lane = threadIdx.x & 31;
    if (warp >= N_TOK) return;
    const float* row = x + (size_t)warp * 256 + lane * 8;
    float v[8];
    *(float4*)&v[0] = *(const float4*)&row[0];
    *(float4*)&v[4] = *(const float4*)&row[4];
    float s = 0.f, sq = 0.f;
#pragma unroll
    for (int j = 0; j < 8; j++) { s += v[j]; sq += v[j] * v[j]; }
#pragma unroll
    for (int off = 16; off; off >>= 1) {
        s  += __shfl_xor_sync(0xffffffffu, s,  off);
        sq += __shfl_xor_sync(0xffffffffu, sq, off);
    }
    float mean = s * (1.f / 256.f);
    float var  = sq * (1.f / 256.f) - mean * mean;
    float inv  = rsqrtf(var + 1e-5f);
    __nv_bfloat16 hi[8], lo[8];
#pragma unroll
    for (int j = 0; j < 8; j++) {
        float y = (v[j] - mean) * inv * g[lane * 8 + j] + b[lane * 8 + j];
        bf16_split(y, hi[j], lo[j]);
    }
    *(uint4*)&g_Aex[(size_t)warp * 512 + lane * 8]       = *(uint4*)hi;
    *(uint4*)&g_Aex[(size_t)warp * 512 + 256 + lane * 8] = *(uint4*)lo;
}

// ---------------- plain expand X -> planes ----------------
__global__ void expand_kernel(const float* __restrict__ src) {
    int n = blockIdx.x;
    int t = threadIdx.x;
    float y = src[n * 256 + t];
    __nv_bfloat16 hi, lo;
    bf16_split(y, hi, lo);
    g_Aex[(size_t)n * 512 + t]       = hi;
    g_Aex[(size_t)n * 512 + 256 + t] = lo;
}

// ---------------- streamed 3-stage bf16 GEMM ----------------
// C[2048, Ncols] = Aplanes[2048, K] @ WBexp[Ncols, 3K]^T + bias
// A: packed plane rows [hi(K)|lo(K)] bf16, stride 2K. B: expanded, stride 3K.
// Tile 64x64, BK=64, 256 threads (8 warps 2x4; warp tile 32x16).
// 3-stage cp.async pipeline (dynamic smem 3x18432B), ONE __syncthreads per chunk.
template<int KDIM, int RELU, int RES, int SPLIT, int EXPAND>
__global__ void __launch_bounds__(256)
fgemm(const __nv_bfloat16* __restrict__ Aex, const __nv_bfloat16* __restrict__ WB,
      const float* __restrict__ bias,
      float* __restrict__ out0, float* __restrict__ out1,
      __nv_bfloat16* __restrict__ Cexp, int Ncols) {
    constexpr int KP    = 3 * KDIM;
    constexpr int NCH   = KP / 64;
    constexpr int ASTR  = 2 * KDIM;             // bf16 stride of A plane rows
    constexpr int STAGE = 64 * 144 * 2;         // bytes per stage (A buf + B buf)

    extern __shared__ char smem[];

    int tid  = threadIdx.x;
    int lane = tid & 31;
    int warp = tid >> 5;
    int wm = (warp & 1) * 32;
    int wn = (warp >> 1) * 16;
    int gq = lane >> 2;
    int tq = lane & 3;

    int m0 = blockIdx.y * 64;
    int n0 = blockIdx.x * 64;

    const uint4* Ag = (const uint4*)(Aex + (size_t)m0 * ASTR);
    const uint4* Bg = (const uint4*)(WB  + (size_t)n0 * KP);

    auto issue = [&](int ic, int st) {
        int kglob = ic * 64;
        int plane = kglob / KDIM;
        int k0    = kglob % KDIM;
        int acol8 = ((plane == 1) ? KDIM + k0 : k0) >> 3;
        int bcol8 = kglob >> 3;
        char* sA = smem + st * STAGE;
        char* sB = sA + 64 * 144;
#pragma unroll
        for (int v = 0; v < 2; v++) {
            int e = v * 256 + tid;
            int row = e >> 3, c8 = e & 7;
            cpa16(su32(sA + row * 144 + c8 * 16), Ag + (size_t)row * (ASTR >> 3) + acol8 + c8);
            cpa16(su32(sB + row * 144 + c8 * 16), Bg + (size_t)row * (KP >> 3)   + bcol8 + c8);
        }
        cpa_commit();
    };
    issue(0, 0);
    if (NCH > 1) issue(1, 1);

    float acc[2][2][4];
#pragma unroll
    for (int mt = 0; mt < 2; mt++)
#pragma unroll
        for (int nt = 0; nt < 2; nt++)
#pragma unroll
            for (int r = 0; r < 4; r++) acc[mt][nt][r] = 0.f;

    int lr8 = lane & 7;
    int sel = lane >> 3;
    int aRow = (sel & 1) * 8 + lr8;
    int aCol = (sel >> 1) * 8;
    int bRow = lane & 15;
    int bCol = (lane >> 4) * 8;

    for (int ic = 0; ic < NCH; ic++) {
        // wait for chunk ic; keep ≤1 younger group in flight
        if (ic + 2 < NCH) cpa_wait<1>();
        else              cpa_wait<0>();
        __syncthreads();                        // all warps done with stage (ic-1)%3 too
        if (ic + 2 < NCH) issue(ic + 2, (ic + 2) % 3);

        int st = ic % 3;
        char* sA = smem + st * STAGE;
        char* sB = sA + 64 * 144;
#pragma unroll
        for (int kk = 0; kk < 4; kk++) {
            int kb = kk * 32;                   // byte offset (16 bf16)
            unsigned a[2][4], b[4];
            ldsm_x4(a[0], su32(sA + (wm + aRow) * 144 + kb + aCol * 2));
            ldsm_x4(a[1], su32(sA + (wm + 16 + aRow) * 144 + kb + aCol * 2));
            ldsm_x4(b,    su32(sB + (wn + bRow) * 144 + kb + bCol * 2));
#pragma unroll
            for (int mt = 0; mt < 2; mt++) {
                mma_bf16(acc[mt][0], a[mt][0], a[mt][1], a[mt][2], a[mt][3], b[0], b[2]);
                mma_bf16(acc[mt][1], a[mt][0], a[mt][1], a[mt][2], a[mt][3], b[1], b[3]);
            }
        }
    }

    // epilogue
#pragma unroll
    for (int mt = 0; mt < 2; mt++) {
#pragma unroll
        for (int half = 0; half < 2; half++) {
            int row = m0 + wm + mt * 16 + gq + half * 8;
#pragma unroll
            for (int nt = 0; nt < 2; nt++) {
                int col = n0 + wn + nt * 8 + 2 * tq;
                float v0 = acc[mt][nt][half * 2 + 0] + bias[col];
                float v1 = acc[mt][nt][half * 2 + 1] + bias[col + 1];
                if (RELU) { v0 = fmaxf(v0, 0.f); v1 = fmaxf(v1, 0.f); }
                if (RES) {
                    float2 old = *(float2*)&out0[(size_t)row * Ncols + col];
                    v0 += old.x; v1 += old.y;
                }
                if (EXPAND) {
                    __nv_bfloat16 h0, l0, h1, l1;
                    bf16_split(v0, h0, l0);
                    bf16_split(v1, h1, l1);
                    size_t base = (size_t)row * 2 * Ncols;
                    Cexp[base + col]             = h0;
                    Cexp[base + col + 1]         = h1;
                    Cexp[base + Ncols + col]     = l0;
                    Cexp[base + Ncols + col + 1] = l1;
                } else if (SPLIT) {
                    if (col < 256) *(float2*)&out0[(size_t)row * 256 + col] = make_float2(v0, v1);
                    else           *(float2*)&out1[(size_t)row * 128 + (col - 256)] = make_float2(v0, v1);
                } else {
                    *(float2*)&out0[(size_t)row * Ncols + col] = make_float2(v0, v1);
                }
            }
        }
    }
}

// ---------------- sparse attention: warp per (query, head); writes planes ----------------
__global__ void attn_kernel() {
    int warp = (blockIdx.x * blockDim.x + threadIdx.x) >> 5;
    int lane = threadIdx.x & 31;
    int n = warp >> 3;
    int h = warp & 7;
    if (n >= N_TOK) return;
    const float scale = 0.17677669529663687f;   // 1/sqrt(32)
    float q = g_QKV[n * 768 + h * 32 + lane];
    int c = g_cnt[n];
    float m = -1e30f, s = 0.f, o = 0.f;
    for (int t = 0; t < c; t++) {
        int j = g_nbr[n * CAP + t];
        float kv = g_QKV[j * 768 + 256 + h * 32 + lane];
        float prod = q * kv;
#pragma unroll
        for (int off = 16; off; off >>= 1) prod += __shfl_xor_sync(0xffffffffu, prod, off);
        float sc = prod * scale;
        float mn = fmaxf(m, sc);
        float corr = __expf(m - mn);
        float p = __expf(sc - mn);
        s = s * corr + p;
        float v = g_QKV[j * 768 + 512 + h * 32 + lane];
        o = o * corr + p * v;
        m = mn;
    }
    float y = o / s;
    __nv_bfloat16 hi, lo;
    bf16_split(y, hi, lo);
    int col = h * 32 + lane;
    g_Aex[(size_t)n * 512 + col]       = hi;
    g_Aex[(size_t)n * 512 + 256 + col] = lo;
}

// ---------------- finals: coords (24-col gemm) + beta head ----------------
__global__ void finals_kernel(const float* __restrict__ Wl2, const float* __restrict__ bl2,
                              const float* __restrict__ Wb2, const float* __restrict__ bb2,
                              float* __restrict__ out) {
    if (blockIdx.x < 192) {
        int idx = blockIdx.x * 256 + threadIdx.x;
        int row = idx / 24;
        int o   = idx % 24;
        const float* a = g_T1 + (size_t)row * 256;
        const float* w = Wl2 + (size_t)o * 256;
        float s = 0.f;
#pragma unroll 8
        for (int k = 0; k < 256; k++) s += a[k] * w[k];
        out[N_TOK + (size_t)row * 24 + o] = s + bl2[o];
    } else {
        int b2 = blockIdx.x - 192;
        int warp = b2 * 8 + (threadIdx.x >> 5);
        int lane = threadIdx.x & 31;
        if (warp >= N_TOK) return;
        float s = 0.f;
#pragma unroll
        for (int k = lane; k < 128; k += 32) s += g_T2[warp * 128 + k] * Wb2[k];
#pragma unroll
        for (int off = 16; off; off >>= 1) s += __shfl_xor_sync(0xffffffffu, s, off);
        if (lane == 0) {
            float z = s + bb2[0];
            float b = 1.f / (1.f + expf(-z));
            b = fminf(fmaxf(b, 1e-6f), 1.f - 1e-6f);
            out[warp] = b;
        }
    }
}

extern "C" void kernel_launch(void* const* d_in, const int* in_sizes, int n_in,
                              void* d_out, int out_size) {
    const float* x_raw = (const float*)d_in[0];
    const float* Win  = (const float*)d_in[2];
    const float* b_in = (const float*)d_in[3];
    const float* Wqkv = (const float*)d_in[4];
    const float* bqkv = (const float*)d_in[5];
    const float* Wo   = (const float*)d_in[6];
    const float* bo   = (const float*)d_in[7];
    const float* W1   = (const float*)d_in[8];
    const float* b1   = (const float*)d_in[9];
    const float* W2   = (const float*)d_in[10];
    const float* b2   = (const float*)d_in[11];
    const float* g1   = (const float*)d_in[12];
    const float* be1  = (const float*)d_in[13];
    const float* g2   = (const float*)d_in[14];
    const float* be2  = (const float*)d_in[15];
    const float* Wl1  = (const float*)d_in[16];
    const float* bl1  = (const float*)d_in[17];
    const float* Wl2  = (const float*)d_in[18];
    const float* bl2  = (const float*)d_in[19];
    const float* Wb1  = (const float*)d_in[20];
    const float* bb1  = (const float*)d_in[21];
    const float* Wb2  = (const float*)d_in[22];
    const float* bb2  = (const float*)d_in[23];
    float* out = (float*)d_out;

    float *pX, *pQKV, *pT1, *pT2, *pbhd;
    cudaGetSymbolAddress((void**)&pX,   g_X);
    cudaGetSymbolAddress((void**)&pQKV, g_QKV);
    cudaGetSymbolAddress((void**)&pT1,  g_T1);
    cudaGetSymbolAddress((void**)&pT2,  g_T2);
    cudaGetSymbolAddress((void**)&pbhd, g_bhd);
    __nv_bfloat16 *pAex, *pFFex, *pWBqkv, *pWBo, *pWB1, *pWB2, *pWBhd;
    cudaGetSymbolAddress((void**)&pAex,   g_Aex);
    cudaGetSymbolAddress((void**)&pFFex,  g_FFex);
    cudaGetSymbolAddress((void**)&pWBqkv, g_WBqkv);
    cudaGetSymbolAddress((void**)&pWBo,   g_WBo);
    cudaGetSymbolAddress((void**)&pWB1,   g_WB1);
    cudaGetSymbolAddress((void**)&pWB2,   g_WB2);
    cudaGetSymbolAddress((void**)&pWBhd,  g_WBhd);

    const int SMEM3 = 3 * 64 * 144 * 2;   // 55296 bytes
    cudaFuncSetAttribute(fgemm<256,0,0,0,0>, cudaFuncAttributeMaxDynamicSharedMemorySize, SMEM3);
    cudaFuncSetAttribute(fgemm<256,0,1,0,0>, cudaFuncAttributeMaxDynamicSharedMemorySize, SMEM3);
    cudaFuncSetAttribute(fgemm<256,1,0,0,1>, cudaFuncAttributeMaxDynamicSharedMemorySize, SMEM3);
    cudaFuncSetAttribute(fgemm<512,0,1,0,0>, cudaFuncAttributeMaxDynamicSharedMemorySize, SMEM3);
    cudaFuncSetAttribute(fgemm<256,1,0,1,0>, cudaFuncAttributeMaxDynamicSharedMemorySize, SMEM3);

    convw_all<<<2048, 256>>>(Wqkv, Wo, W1, W2, Wl1, Wb1, bl1, bb1);
    embed_kernel<<<N_TOK, HDIM>>>(x_raw, Win, b_in);
    build_nbr_kernel<<<N_TOK / 8, 256>>>();

    for (int l = 0; l < NLAYER; l++) {
        const __nv_bfloat16* WBqkv_l = pWBqkv + (size_t)l * 768 * 768;
        const __nv_bfloat16* WBo_l   = pWBo   + (size_t)l * 256 * 768;
        const __nv_bfloat16* WB1_l   = pWB1   + (size_t)l * 512 * 768;
        const __nv_bfloat16* WB2_l   = pWB2   + (size_t)l * 256 * 1536;

        ln_expand<<<N_TOK / 8, 256>>>(pX, g1 + l * 256, be1 + l * 256);
        fgemm<256,0,0,0,0><<<dim3(12, 32), 256, SMEM3>>>(
            pAex, WBqkv_l, bqkv + l * 768, pQKV, nullptr, nullptr, 768);
        attn_kernel<<<(N_TOK * 8 * 32) / 256, 256>>>();
        fgemm<256,0,1,0,0><<<dim3(4, 32), 256, SMEM3>>>(
            pAex, WBo_l, bo + l * 256, pX, nullptr, nullptr, 256);
        ln_expand<<<N_TOK / 8, 256>>>(pX, g2 + l * 256, be2 + l * 256);
        fgemm<256,1,0,0,1><<<dim3(8, 32), 256, SMEM3>>>(
            pAex, WB1_l, b1 + l * 512, nullptr, nullptr, pFFex, 512);
        fgemm<512,0,1,0,0><<<dim3(4, 32), 256, SMEM3>>>(
            pFFex, WB2_l, b2 + l * 256, pX, nullptr, nullptr, 256);
    }

    // heads
    expand_kernel<<<N_TOK, HDIM>>>(pX);
    fgemm<256,1,0,1,0><<<dim3(6, 32), 256, SMEM3>>>(
        pAex, pWBhd, pbhd, pT1, pT2, nullptr, 384);
    finals_kernel<<<448, 256>>>(Wl2, bl2, Wb2, bb2, out);
}

// round 15
// speedup vs baseline: 2.8375x; 1.0037x over previous
#include <cuda_runtime.h>
#include <cuda_bf16.h>
#include <stdint.h>
#include <math.h>

#define N_TOK 2048
#define HDIM  256
#define FFDIM 512
#define NLAYER 6
#define CAP   96

// ---------------- device scratch ----------------
__device__ float g_X  [N_TOK * HDIM];
__device__ float g_QKV[N_TOK * 3 * HDIM];
__device__ float g_T1 [N_TOK * HDIM];
__device__ float g_T2 [N_TOK * (HDIM/2)];
__device__ float g_eta[N_TOK];
__device__ float g_phi[N_TOK];
__device__ int   g_nbr[N_TOK * CAP];
__device__ int   g_cnt[N_TOK];

// packed bf16 activation planes: row = [hi(0..K-1) | lo(0..K-1)]
__device__ __nv_bfloat16 g_Aex [N_TOK * 512];    // K=256 sources (LN out / attn out / X)
__device__ __nv_bfloat16 g_FFex[N_TOK * 1024];   // K=512 (FF1 out)

// expanded bf16 weights (K' = 3K): planes [hi | hi | lo] along K'
__device__ __nv_bfloat16 g_WBqkv[NLAYER * 768 * 768];
__device__ __nv_bfloat16 g_WBo  [NLAYER * 256 * 768];
__device__ __nv_bfloat16 g_WB1  [NLAYER * 512 * 768];
__device__ __nv_bfloat16 g_WB2  [NLAYER * 256 * 1536];
__device__ __nv_bfloat16 g_WBhd [384 * 768];     // Wl1 (256 rows) ++ Wb1 (128 rows)
__device__ float         g_bhd  [384];           // bl1 ++ bb1

// ---------------- helpers ----------------
__device__ __forceinline__ unsigned su32(const void* p) {
    return (unsigned)__cvta_generic_to_shared(p);
}
__device__ __forceinline__ void bf16_split(float x, __nv_bfloat16& hi, __nv_bfloat16& lo) {
    hi = __float2bfloat16(x);
    lo = __float2bfloat16(x - __bfloat162float(hi));
}
__device__ __forceinline__ void mma_bf16(float c[4],
                                         unsigned a0, unsigned a1, unsigned a2, unsigned a3,
                                         unsigned b0, unsigned b1) {
    asm volatile(
        "mma.sync.aligned.m16n8k16.row.col.f32.bf16.bf16.f32 "
        "{%0,%1,%2,%3}, {%4,%5,%6,%7}, {%8,%9}, {%0,%1,%2,%3};\n"
        : "+f"(c[0]), "+f"(c[1]), "+f"(c[2]), "+f"(c[3])
        : "r"(a0), "r"(a1), "r"(a2), "r"(a3), "r"(b0), "r"(b1));
}
__device__ __forceinline__ void ldsm_x4(unsigned r[4], unsigned addr) {
    asm volatile("ldmatrix.sync.aligned.m8n8.x4.shared.b16 {%0,%1,%2,%3}, [%4];"
                 : "=r"(r[0]), "=r"(r[1]), "=r"(r[2]), "=r"(r[3]) : "r"(addr));
}
__device__ __forceinline__ void cpa16(unsigned saddr, const void* g) {
    asm volatile("cp.async.ca.shared.global [%0], [%1], 16;" :: "r"(saddr), "l"(g));
}
__device__ __forceinline__ void cpa_commit() {
    asm volatile("cp.async.commit_group;" ::: "memory");
}
template<int N> __device__ __forceinline__ void cpa_wait() {
    asm volatile("cp.async.wait_group %0;" :: "n"(N) : "memory");
}

// ---------------- merged weight expansion ----------------
__global__ void convw_all(const float* __restrict__ Wqkv, const float* __restrict__ Wo,
                          const float* __restrict__ W1,   const float* __restrict__ W2,
                          const float* __restrict__ Wl1,  const float* __restrict__ Wb1,
                          const float* __restrict__ bl1,  const float* __restrict__ bb1) {
    const long n0 = 6L * 768 * 256;
    const long n1 = n0 + 6L * 256 * 256;
    const long n2 = n1 + 6L * 512 * 256;
    const long n3 = n2 + 6L * 256 * 512;
    const long n4 = n3 + 256L * 256;
    const long n5 = n4 + 128L * 256;
    const long n6 = n5 + 384;
    for (long idx = (long)blockIdx.x * blockDim.x + threadIdx.x; idx < n6;
         idx += (long)gridDim.x * blockDim.x) {
        if (idx >= n5) {
            int i = (int)(idx - n5);
            g_bhd[i] = (i < 256) ? bl1[i] : bb1[i - 256];
            continue;
        }
        const float* src; __nv_bfloat16* dst; long loc; int K;
        if (idx < n0)      { src = Wqkv; dst = g_WBqkv; loc = idx;      K = 256; }
        else if (idx < n1) { src = Wo;   dst = g_WBo;   loc = idx - n0; K = 256; }
        else if (idx < n2) { src = W1;   dst = g_WB1;   loc = idx - n1; K = 256; }
        else if (idx < n3) { src = W2;   dst = g_WB2;   loc = idx - n2; K = 512; }
        else if (idx < n4) { src = Wl1;  dst = g_WBhd;  loc = idx - n3; K = 256; }
        else               { src = Wb1;  dst = g_WBhd + 256L * 768; loc = idx - n4; K = 256; }
        int k = (int)(loc % K);
        long t = loc / K;
        float x = src[loc];
        __nv_bfloat16 hi, lo;
        bf16_split(x, hi, lo);
        long base = t * (3L * K);
        dst[base + k]        = hi;     // plane 0: hi   (pairs A-hi)
        dst[base + K + k]    = hi;     // plane 1: hi   (pairs A-lo)
        dst[base + 2L*K + k] = lo;     // plane 2: lo   (pairs A-hi)
    }
}

// ---------------- embed ----------------
__global__ void embed_kernel(const float* __restrict__ xr,
                             const float* __restrict__ Win,
                             const float* __restrict__ b_in) {
    int n = blockIdx.x;
    int h = threadIdx.x;
    __shared__ float r[8];
    if (h < 8) r[h] = xr[n * 8 + h];
    __syncthreads();
    float acc = b_in[h];
#pragma unroll
    for (int k = 0; k < 8; k++) acc += r[k] * Win[h * 8 + k];
    g_X[n * HDIM + h] = acc;
    if (h == 0) {
        g_eta[n] = r[1] * 5.24f   - 2.62f;
        g_phi[n] = r[2] * 6.2832f - 3.1416f;
    }
}

// ---------------- neighbor list ----------------
__global__ void build_nbr_kernel() {
    int warp = (blockIdx.x * blockDim.x + threadIdx.x) >> 5;
    int lane = threadIdx.x & 31;
    if (warp >= N_TOK) return;
    int i = warp;
    float ei = g_eta[i], pi = g_phi[i];
    int c = 0;
    for (int j0 = 0; j0 < N_TOK; j0 += 32) {
        int j = j0 + lane;
        float de = ei - g_eta[j];
        float dp = pi - g_phi[j];
        dp = dp - 6.283185307179586f * rintf(dp * 0.15915494309189535f);
        float dr2 = de * de + dp * dp;
        bool keep = (dr2 <= 0.04f);
        unsigned m = __ballot_sync(0xffffffffu, keep);
        if (keep) {
            int pos = c + __popc(m & ((1u << lane) - 1u));
            if (pos < CAP) g_nbr[i * CAP + pos] = j;
        }
        c += __popc(m);
    }
    if (lane == 0) g_cnt[i] = (c < CAP) ? c : CAP;
}

// ---------------- LN -> packed planes (warp per row) ----------------
__global__ void ln_expand(const float* __restrict__ x,
                          const float* __restrict__ g,
                          const float* __restrict__ b) {
    int warp = (blockIdx.x * blockDim.x + threadIdx.x) >> 5;   // row
    int lane = threadIdx.x & 31;
    if (warp >= N_TOK) return;
    const float* row = x + (size_t)warp * 256 + lane * 8;
    float v[8];
    *(float4*)&v[0] = *(const float4*)&row[0];
    *(float4*)&v[4] = *(const float4*)&row[4];
    float s = 0.f, sq = 0.f;
#pragma unroll
    for (int j = 0; j < 8; j++) { s += v[j]; sq += v[j] * v[j]; }
#pragma unroll
    for (int off = 16; off; off >>= 1) {
        s  += __shfl_xor_sync(0xffffffffu, s,  off);
        sq += __shfl_xor_sync(0xffffffffu, sq, off);
    }
    float mean = s * (1.f / 256.f);
    float var  = sq * (1.f / 256.f) - mean * mean;
    float inv  = rsqrtf(var + 1e-5f);
    __nv_bfloat16 hi[8], lo[8];
#pragma unroll
    for (int j = 0; j < 8; j++) {
        float y = (v[j] - mean) * inv * g[lane * 8 + j] + b[lane * 8 + j];
        bf16_split(y, hi[j], lo[j]);
    }
    *(uint4*)&g_Aex[(size_t)warp * 512 + lane * 8]       = *(uint4*)hi;
    *(uint4*)&g_Aex[(size_t)warp * 512 + 256 + lane * 8] = *(uint4*)lo;
}

// ---------------- plain expand X -> planes ----------------
__global__ void expand_kernel(const float* __restrict__ src) {
    int n = blockIdx.x;
    int t = threadIdx.x;
    float y = src[n * 256 + t];
    __nv_bfloat16 hi, lo;
    bf16_split(y, hi, lo);
    g_Aex[(size_t)n * 512 + t]       = hi;
    g_Aex[(size_t)n * 512 + 256 + t] = lo;
}

// ---------------- streamed 3-stage bf16 GEMM, 64x64 tile ----------------
template<int KDIM, int RELU, int RES, int SPLIT, int EXPAND>
__global__ void __launch_bounds__(256)
fgemm(const __nv_bfloat16* __restrict__ Aex, const __nv_bfloat16* __restrict__ WB,
      const float* __restrict__ bias,
      float* __restrict__ out0, float* __restrict__ out1,
      __nv_bfloat16* __restrict__ Cexp, int Ncols) {
    constexpr int KP    = 3 * KDIM;
    constexpr int NCH   = KP / 64;
    constexpr int ASTR  = 2 * KDIM;
    constexpr int STAGE = 64 * 144 * 2;

    extern __shared__ char smem[];

    int tid  = threadIdx.x;
    int lane = tid & 31;
    int warp = tid >> 5;
    int wm = (warp & 1) * 32;
    int wn = (warp >> 1) * 16;
    int gq = lane >> 2;
    int tq = lane & 3;

    int m0 = blockIdx.y * 64;
    int n0 = blockIdx.x * 64;

    const uint4* Ag = (const uint4*)(Aex + (size_t)m0 * ASTR);
    const uint4* Bg = (const uint4*)(WB  + (size_t)n0 * KP);

    auto issue = [&](int ic, int st) {
        int kglob = ic * 64;
        int plane = kglob / KDIM;
        int k0    = kglob % KDIM;
        int acol8 = ((plane == 1) ? KDIM + k0 : k0) >> 3;
        int bcol8 = kglob >> 3;
        char* sA = smem + st * STAGE;
        char* sB = sA + 64 * 144;
#pragma unroll
        for (int v = 0; v < 2; v++) {
            int e = v * 256 + tid;
            int row = e >> 3, c8 = e & 7;
            cpa16(su32(sA + row * 144 + c8 * 16), Ag + (size_t)row * (ASTR >> 3) + acol8 + c8);
            cpa16(su32(sB + row * 144 + c8 * 16), Bg + (size_t)row * (KP >> 3)   + bcol8 + c8);
        }
        cpa_commit();
    };
    issue(0, 0);
    if (NCH > 1) issue(1, 1);

    float acc[2][2][4];
#pragma unroll
    for (int mt = 0; mt < 2; mt++)
#pragma unroll
        for (int nt = 0; nt < 2; nt++)
#pragma unroll
            for (int r = 0; r < 4; r++) acc[mt][nt][r] = 0.f;

    int lr8 = lane & 7;
    int sel = lane >> 3;
    int aRow = (sel & 1) * 8 + lr8;
    int aCol = (sel >> 1) * 8;
    int bRow = lane & 15;
    int bCol = (lane >> 4) * 8;

    for (int ic = 0; ic < NCH; ic++) {
        if (ic + 2 < NCH) cpa_wait<1>();
        else              cpa_wait<0>();
        __syncthreads();
        if (ic + 2 < NCH) issue(ic + 2, (ic + 2) % 3);

        int st = ic % 3;
        char* sA = smem + st * STAGE;
        char* sB = sA + 64 * 144;
#pragma unroll
        for (int kk = 0; kk < 4; kk++) {
            int kb = kk * 32;
            unsigned a[2][4], b[4];
            ldsm_x4(a[0], su32(sA + (wm + aRow) * 144 + kb + aCol * 2));
            ldsm_x4(a[1], su32(sA + (wm + 16 + aRow) * 144 + kb + aCol * 2));
            ldsm_x4(b,    su32(sB + (wn + bRow) * 144 + kb + bCol * 2));
#pragma unroll
            for (int mt = 0; mt < 2; mt++) {
                mma_bf16(acc[mt][0], a[mt][0], a[mt][1], a[mt][2], a[mt][3], b[0], b[2]);
                mma_bf16(acc[mt][1], a[mt][0], a[mt][1], a[mt][2], a[mt][3], b[1], b[3]);
            }
        }
    }

#pragma unroll
    for (int mt = 0; mt < 2; mt++) {
#pragma unroll
        for (int half = 0; half < 2; half++) {
            int row = m0 + wm + mt * 16 + gq + half * 8;
#pragma unroll
            for (int nt = 0; nt < 2; nt++) {
                int col = n0 + wn + nt * 8 + 2 * tq;
                float v0 = acc[mt][nt][half * 2 + 0] + bias[col];
                float v1 = acc[mt][nt][half * 2 + 1] + bias[col + 1];
                if (RELU) { v0 = fmaxf(v0, 0.f); v1 = fmaxf(v1, 0.f); }
                if (RES) {
                    float2 old = *(float2*)&out0[(size_t)row * Ncols + col];
                    v0 += old.x; v1 += old.y;
                }
                if (EXPAND) {
                    __nv_bfloat16 h0, l0, h1, l1;
                    bf16_split(v0, h0, l0);
                    bf16_split(v1, h1, l1);
                    size_t base = (size_t)row * 2 * Ncols;
                    Cexp[base + col]             = h0;
                    Cexp[base + col + 1]         = h1;
                    Cexp[base + Ncols + col]     = l0;
                    Cexp[base + Ncols + col + 1] = l1;
                } else if (SPLIT) {
                    if (col < 256) *(float2*)&out0[(size_t)row * 256 + col] = make_float2(v0, v1);
                    else           *(float2*)&out1[(size_t)row * 128 + (col - 256)] = make_float2(v0, v1);
                } else {
                    *(float2*)&out0[(size_t)row * Ncols + col] = make_float2(v0, v1);
                }
            }
        }
    }
}

// ---------------- streamed 3-stage bf16 GEMM, 128x64 tile (big-N GEMMs) ----------------
// 8 warps as 4(M) x 2(N); warp tile 32x32. 8 MACs/smem-byte, MMA:LDSM = 2:1.
template<int KDIM, int RELU, int EXPAND>
__global__ void __launch_bounds__(256)
fgemm128(const __nv_bfloat16* __restrict__ Aex, const __nv_bfloat16* __restrict__ WB,
         const float* __restrict__ bias,
         float* __restrict__ out0, __nv_bfloat16* __restrict__ Cexp, int Ncols) {
    constexpr int KP    = 3 * KDIM;
    constexpr int NCH   = KP / 64;
    constexpr int ASTR  = 2 * KDIM;
    constexpr int STAGE = 192 * 144;            // A 128 rows + B 64 rows

    extern __shared__ char smem[];

    int tid  = threadIdx.x;
    int lane = tid & 31;
    int warp = tid >> 5;
    int wm = (warp >> 1) * 32;                  // 0,32,64,96
    int wn = (warp & 1)  * 32;                  // 0,32
    int gq = lane >> 2;
    int tq = lane & 3;

    int m0 = blockIdx.y * 128;
    int n0 = blockIdx.x * 64;

    const uint4* Ag = (const uint4*)(Aex + (size_t)m0 * ASTR);
    const uint4* Bg = (const uint4*)(WB  + (size_t)n0 * KP);

    auto issue = [&](int ic, int st) {
        int kglob = ic * 64;
        int plane = kglob / KDIM;
        int k0    = kglob % KDIM;
        int acol8 = ((plane == 1) ? KDIM + k0 : k0) >> 3;
        int bcol8 = kglob >> 3;
        char* sA = smem + st * STAGE;
        char* sB = sA + 128 * 144;
#pragma unroll
        for (int v = 0; v < 4; v++) {           // A: 128*8=1024 vecs
            int e = v * 256 + tid;
            int row = e >> 3, c8 = e & 7;
            cpa16(su32(sA + row * 144 + c8 * 16), Ag + (size_t)row * (ASTR >> 3) + acol8 + c8);
        }
#pragma unroll
        for (int v = 0; v < 2; v++) {           // B: 64*8=512 vecs
            int e = v * 256 + tid;
            int row = e >> 3, c8 = e & 7;
            cpa16(su32(sB + row * 144 + c8 * 16), Bg + (size_t)row * (KP >> 3) + bcol8 + c8);
        }
        cpa_commit();
    };
    issue(0, 0);
    if (NCH > 1) issue(1, 1);

    float acc[2][4][4];
#pragma unroll
    for (int mt = 0; mt < 2; mt++)
#pragma unroll
        for (int nt = 0; nt < 4; nt++)
#pragma unroll
            for (int r = 0; r < 4; r++) acc[mt][nt][r] = 0.f;

    int lr8 = lane & 7;
    int sel = lane >> 3;
    int aRow = (sel & 1) * 8 + lr8;
    int aCol = (sel >> 1) * 8;
    int bRow = lane & 15;
    int bCol = (lane >> 4) * 8;

    for (int ic = 0; ic < NCH; ic++) {
        if (ic + 2 < NCH) cpa_wait<1>();
        else              cpa_wait<0>();
        __syncthreads();
        if (ic + 2 < NCH) issue(ic + 2, (ic + 2) % 3);

        int st = ic % 3;
        char* sA = smem + st * STAGE;
        char* sB = sA + 128 * 144;
#pragma unroll
        for (int kk = 0; kk < 4; kk++) {
            int kb = kk * 32;
            unsigned a[2][4], b[2][4];
            ldsm_x4(a[0], su32(sA + (wm + aRow) * 144 + kb + aCol * 2));
            ldsm_x4(a[1], su32(sA + (wm + 16 + aRow) * 144 + kb + aCol * 2));
            ldsm_x4(b[0], su32(sB + (wn + bRow) * 144 + kb + bCol * 2));
            ldsm_x4(b[1], su32(sB + (wn + 16 + bRow) * 144 + kb + bCol * 2));
#pragma unroll
            for (int mt = 0; mt < 2; mt++)
#pragma unroll
                for (int nt = 0; nt < 4; nt++)
                    mma_bf16(acc[mt][nt], a[mt][0], a[mt][1], a[mt][2], a[mt][3],
                             b[nt >> 1][nt & 1], b[nt >> 1][(nt & 1) + 2]);
        }
    }

#pragma unroll
    for (int mt = 0; mt < 2; mt++) {
#pragma unroll
        for (int half = 0; half < 2; half++) {
            int row = m0 + wm + mt * 16 + gq + half * 8;
#pragma unroll
            for (int nt = 0; nt < 4; nt++) {
                int col = n0 + wn + nt * 8 + 2 * tq;
                float v0 = acc[mt][nt][half * 2 + 0] + bias[col];
                float v1 = acc[mt][nt][half * 2 + 1] + bias[col + 1];
                if (RELU) { v0 = fmaxf(v0, 0.f); v1 = fmaxf(v1, 0.f); }
                if (EXPAND) {
                    __nv_bfloat16 h0, l0, h1, l1;
                    bf16_split(v0, h0, l0);
                    bf16_split(v1, h1, l1);
                    size_t base = (size_t)row * 2 * Ncols;
                    Cexp[base + col]             = h0;
                    Cexp[base + col + 1]         = h1;
                    Cexp[base + Ncols + col]     = l0;
                    Cexp[base + Ncols + col + 1] = l1;
                } else {
                    *(float2*)&out0[(size_t)row * Ncols + col] = make_float2(v0, v1);
                }
            }
        }
    }
}

// ---------------- sparse attention: warp per (query, head); writes planes ----------------
__global__ void attn_kernel() {
    int warp = (blockIdx.x * blockDim.x + threadIdx.x) >> 5;
    int lane = threadIdx.x & 31;
    int n = warp >> 3;
    int h = warp & 7;
    if (n >= N_TOK) return;
    const float scale = 0.17677669529663687f;   // 1/sqrt(32)
    float q = g_QKV[n * 768 + h * 32 + lane];
    int c = g_cnt[n];
    float m = -1e30f, s = 0.f, o = 0.f;
    for (int t = 0; t < c; t++) {
        int j = g_nbr[n * CAP + t];
        float kv = g_QKV[j * 768 + 256 + h * 32 + lane];
        float prod = q * kv;
#pragma unroll
        for (int off = 16; off; off >>= 1) prod += __shfl_xor_sync(0xffffffffu, prod, off);
        float sc = prod * scale;
        float mn = fmaxf(m, sc);
        float corr = __expf(m - mn);
        float p = __expf(sc - mn);
        s = s * corr + p;
        float v = g_QKV[j * 768 + 512 + h * 32 + lane];
        o = o * corr + p * v;
        m = mn;
    }
    float y = o / s;
    __nv_bfloat16 hi, lo;
    bf16_split(y, hi, lo);
    int col = h * 32 + lane;
    g_Aex[(size_t)n * 512 + col]       = hi;
    g_Aex[(size_t)n * 512 + 256 + col] = lo;
}

// ---------------- finals: coords (24-col gemm) + beta head ----------------
__global__ void finals_kernel(const float* __restrict__ Wl2, const float* __restrict__ bl2,
                              const float* __restrict__ Wb2, const float* __restrict__ bb2,
                              float* __restrict__ out) {
    if (blockIdx.x < 192) {
        int idx = blockIdx.x * 256 + threadIdx.x;
        int row = idx / 24;
        int o   = idx % 24;
        const float* a = g_T1 + (size_t)row * 256;
        const float* w = Wl2 + (size_t)o * 256;
        float s = 0.f;
#pragma unroll 8
        for (int k = 0; k < 256; k++) s += a[k] * w[k];
        out[N_TOK + (size_t)row * 24 + o] = s + bl2[o];
    } else {
        int b2 = blockIdx.x - 192;
        int warp = b2 * 8 + (threadIdx.x >> 5);
        int lane = threadIdx.x & 31;
        if (warp >= N_TOK) return;
        float s = 0.f;
#pragma unroll
        for (int k = lane; k < 128; k += 32) s += g_T2[warp * 128 + k] * Wb2[k];
#pragma unroll
        for (int off = 16; off; off >>= 1) s += __shfl_xor_sync(0xffffffffu, s, off);
        if (lane == 0) {
            float z = s + bb2[0];
            float b = 1.f / (1.f + expf(-z));
            b = fminf(fmaxf(b, 1e-6f), 1.f - 1e-6f);
            out[warp] = b;
        }
    }
}

extern "C" void kernel_launch(void* const* d_in, const int* in_sizes, int n_in,
                              void* d_out, int out_size) {
    const float* x_raw = (const float*)d_in[0];
    const float* Win  = (const float*)d_in[2];
    const float* b_in = (const float*)d_in[3];
    const float* Wqkv = (const float*)d_in[4];
    const float* bqkv = (const float*)d_in[5];
    const float* Wo   = (const float*)d_in[6];
    const float* bo   = (const float*)d_in[7];
    const float* W1   = (const float*)d_in[8];
    const float* b1   = (const float*)d_in[9];
    const float* W2   = (const float*)d_in[10];
    const float* b2   = (const float*)d_in[11];
    const float* g1   = (const float*)d_in[12];
    const float* be1  = (const float*)d_in[13];
    const float* g2   = (const float*)d_in[14];
    const float* be2  = (const float*)d_in[15];
    const float* Wl1  = (const float*)d_in[16];
    const float* bl1  = (const float*)d_in[17];
    const float* Wl2  = (const float*)d_in[18];
    const float* bl2  = (const float*)d_in[19];
    const float* Wb1  = (const float*)d_in[20];
    const float* bb1  = (const float*)d_in[21];
    const float* Wb2  = (const float*)d_in[22];
    const float* bb2  = (const float*)d_in[23];
    float* out = (float*)d_out;

    float *pX, *pQKV, *pT1, *pT2, *pbhd;
    cudaGetSymbolAddress((void**)&pX,   g_X);
    cudaGetSymbolAddress((void**)&pQKV, g_QKV);
    cudaGetSymbolAddress((void**)&pT1,  g_T1);
    cudaGetSymbolAddress((void**)&pT2,  g_T2);
    cudaGetSymbolAddress((void**)&pbhd, g_bhd);
    __nv_bfloat16 *pAex, *pFFex, *pWBqkv, *pWBo, *pWB1, *pWB2, *pWBhd;
    cudaGetSymbolAddress((void**)&pAex,   g_Aex);
    cudaGetSymbolAddress((void**)&pFFex,  g_FFex);
    cudaGetSymbolAddress((void**)&pWBqkv, g_WBqkv);
    cudaGetSymbolAddress((void**)&pWBo,   g_WBo);
    cudaGetSymbolAddress((void**)&pWB1,   g_WB1);
    cudaGetSymbolAddress((void**)&pWB2,   g_WB2);
    cudaGetSymbolAddress((void**)&pWBhd,  g_WBhd);

    const int SMEM3  = 3 * 64 * 144 * 2;    // 55296
    const int SMEM3B = 3 * 192 * 144;       // 82944
    cudaFuncSetAttribute(fgemm<256,0,1,0,0>,  cudaFuncAttributeMaxDynamicSharedMemorySize, SMEM3);
    cudaFuncSetAttribute(fgemm<512,0,1,0,0>,  cudaFuncAttributeMaxDynamicSharedMemorySize, SMEM3);
    cudaFuncSetAttribute(fgemm<256,1,0,1,0>,  cudaFuncAttributeMaxDynamicSharedMemorySize, SMEM3);
    cudaFuncSetAttribute(fgemm128<256,0,0>,   cudaFuncAttributeMaxDynamicSharedMemorySize, SMEM3B);
    cudaFuncSetAttribute(fgemm128<256,1,1>,   cudaFuncAttributeMaxDynamicSharedMemorySize, SMEM3B);

    convw_all<<<2048, 256>>>(Wqkv, Wo, W1, W2, Wl1, Wb1, bl1, bb1);
    embed_kernel<<<N_TOK, HDIM>>>(x_raw, Win, b_in);
    build_nbr_kernel<<<N_TOK / 8, 256>>>();

    for (int l = 0; l < NLAYER; l++) {
        const __nv_bfloat16* WBqkv_l = pWBqkv + (size_t)l * 768 * 768;
        const __nv_bfloat16* WBo_l   = pWBo   + (size_t)l * 256 * 768;
        const __nv_bfloat16* WB1_l   = pWB1   + (size_t)l * 512 * 768;
        const __nv_bfloat16* WB2_l   = pWB2   + (size_t)l * 256 * 1536;

        ln_expand<<<N_TOK / 8, 256>>>(pX, g1 + l * 256, be1 + l * 256);
        fgemm128<256,0,0><<<dim3(12, 16), 256, SMEM3B>>>(
            pAex, WBqkv_l, bqkv + l * 768, pQKV, nullptr, 768);
        attn_kernel<<<(N_TOK * 8 * 32) / 256, 256>>>();
        fgemm<256,0,1,0,0><<<dim3(4, 32), 256, SMEM3>>>(
            pAex, WBo_l, bo + l * 256, pX, nullptr, nullptr, 256);
        ln_expand<<<N_TOK / 8, 256>>>(pX, g2 + l * 256, be2 + l * 256);
        fgemm128<256,1,1><<<dim3(8, 16), 256, SMEM3B>>>(
            pAex, WB1_l, b1 + l * 512, nullptr, pFFex, 512);
        fgemm<512,0,1,0,0><<<dim3(4, 32), 256, SMEM3>>>(
            pFFex, WB2_l, b2 + l * 256, pX, nullptr, nullptr, 256);
    }

    // heads
    expand_kernel<<<N_TOK, HDIM>>>(pX);
    fgemm<256,1,0,1,0><<<dim3(6, 32), 256, SMEM3>>>(
        pAex, pWBhd, pbhd, pT1, pT2, nullptr, 384);
    finals_kernel<<<448, 256>>>(Wl2, bl2, Wb2, bb2, out);
}

// round 16
// speedup vs baseline: 3.0156x; 1.0628x over previous
#include <cuda_runtime.h>
#include <cuda_bf16.h>
#include <stdint.h>
#include <math.h>

#define N_TOK 2048
#define HDIM  256
#define FFDIM 512
#define NLAYER 6
#define CAP   96

// ---------------- device scratch ----------------
__device__ float g_X  [N_TOK * HDIM];
__device__ float g_QKV[N_TOK * 3 * HDIM];
__device__ float g_T1 [N_TOK * HDIM];
__device__ float g_T2 [N_TOK * (HDIM/2)];
__device__ float g_eta[N_TOK];
__device__ float g_phi[N_TOK];
__device__ int   g_nbr[N_TOK * CAP];
__device__ int   g_cnt[N_TOK];

// packed bf16 activation planes: row = [hi(0..K-1) | lo(0..K-1)]
__device__ __nv_bfloat16 g_Aex [N_TOK * 512];    // K=256 sources
__device__ __nv_bfloat16 g_FFex[N_TOK * 1024];   // K=512 (FF1 out)

// expanded bf16 weights (K' = 3K): planes [hi | hi | lo] along K'
__device__ __nv_bfloat16 g_WBqkv[NLAYER * 768 * 768];
__device__ __nv_bfloat16 g_WBo  [NLAYER * 256 * 768];
__device__ __nv_bfloat16 g_WB1  [NLAYER * 512 * 768];
__device__ __nv_bfloat16 g_WB2  [NLAYER * 256 * 1536];
__device__ __nv_bfloat16 g_WBhd [384 * 768];     // Wl1 (256 rows) ++ Wb1 (128 rows)
__device__ float         g_bhd  [384];           // bl1 ++ bb1

// ---------------- helpers ----------------
__device__ __forceinline__ unsigned su32(const void* p) {
    return (unsigned)__cvta_generic_to_shared(p);
}
__device__ __forceinline__ void bf16_split(float x, __nv_bfloat16& hi, __nv_bfloat16& lo) {
    hi = __float2bfloat16(x);
    lo = __float2bfloat16(x - __bfloat162float(hi));
}
__device__ __forceinline__ void mma_bf16(float c[4],
                                         unsigned a0, unsigned a1, unsigned a2, unsigned a3,
                                         unsigned b0, unsigned b1) {
    asm volatile(
        "mma.sync.aligned.m16n8k16.row.col.f32.bf16.bf16.f32 "
        "{%0,%1,%2,%3}, {%4,%5,%6,%7}, {%8,%9}, {%0,%1,%2,%3};\n"
        : "+f"(c[0]), "+f"(c[1]), "+f"(c[2]), "+f"(c[3])
        : "r"(a0), "r"(a1), "r"(a2), "r"(a3), "r"(b0), "r"(b1));
}
__device__ __forceinline__ void ldsm_x4(unsigned r[4], unsigned addr) {
    asm volatile("ldmatrix.sync.aligned.m8n8.x4.shared.b16 {%0,%1,%2,%3}, [%4];"
                 : "=r"(r[0]), "=r"(r[1]), "=r"(r[2]), "=r"(r[3]) : "r"(addr));
}
__device__ __forceinline__ void cpa16(unsigned saddr, const void* g) {
    asm volatile("cp.async.ca.shared.global [%0], [%1], 16;" :: "r"(saddr), "l"(g));
}
__device__ __forceinline__ void cpa_commit() {
    asm volatile("cp.async.commit_group;" ::: "memory");
}
template<int N> __device__ __forceinline__ void cpa_wait() {
    asm volatile("cp.async.wait_group %0;" :: "n"(N) : "memory");
}

// ---------------- merged weight expansion ----------------
__global__ void convw_all(const float* __restrict__ Wqkv, const float* __restrict__ Wo,
                          const float* __restrict__ W1,   const float* __restrict__ W2,
                          const float* __restrict__ Wl1,  const float* __restrict__ Wb1,
                          const float* __restrict__ bl1,  const float* __restrict__ bb1) {
    const long n0 = 6L * 768 * 256;
    const long n1 = n0 + 6L * 256 * 256;
    const long n2 = n1 + 6L * 512 * 256;
    const long n3 = n2 + 6L * 256 * 512;
    const long n4 = n3 + 256L * 256;
    const long n5 = n4 + 128L * 256;
    const long n6 = n5 + 384;
    for (long idx = (long)blockIdx.x * blockDim.x + threadIdx.x; idx < n6;
         idx += (long)gridDim.x * blockDim.x) {
        if (idx >= n5) {
            int i = (int)(idx - n5);
            g_bhd[i] = (i < 256) ? bl1[i] : bb1[i - 256];
            continue;
        }
        const float* src; __nv_bfloat16* dst; long loc; int K;
        if (idx < n0)      { src = Wqkv; dst = g_WBqkv; loc = idx;      K = 256; }
        else if (idx < n1) { src = Wo;   dst = g_WBo;   loc = idx - n0; K = 256; }
        else if (idx < n2) { src = W1;   dst = g_WB1;   loc = idx - n1; K = 256; }
        else if (idx < n3) { src = W2;   dst = g_WB2;   loc = idx - n2; K = 512; }
        else if (idx < n4) { src = Wl1;  dst = g_WBhd;  loc = idx - n3; K = 256; }
        else               { src = Wb1;  dst = g_WBhd + 256L * 768; loc = idx - n4; K = 256; }
        int k = (int)(loc % K);
        long t = loc / K;
        float x = src[loc];
        __nv_bfloat16 hi, lo;
        bf16_split(x, hi, lo);
        long base = t * (3L * K);
        dst[base + k]        = hi;     // plane 0: hi   (pairs A-hi)
        dst[base + K + k]    = hi;     // plane 1: hi   (pairs A-lo)
        dst[base + 2L*K + k] = lo;     // plane 2: lo   (pairs A-hi)
    }
}

// ---------------- embed ----------------
__global__ void embed_kernel(const float* __restrict__ xr,
                             const float* __restrict__ Win,
                             const float* __restrict__ b_in) {
    int n = blockIdx.x;
    int h = threadIdx.x;
    __shared__ float r[8];
    if (h < 8) r[h] = xr[n * 8 + h];
    __syncthreads();
    float acc = b_in[h];
#pragma unroll
    for (int k = 0; k < 8; k++) acc += r[k] * Win[h * 8 + k];
    g_X[n * HDIM + h] = acc;
    if (h == 0) {
        g_eta[n] = r[1] * 5.24f   - 2.62f;
        g_phi[n] = r[2] * 6.2832f - 3.1416f;
    }
}

// ---------------- neighbor list ----------------
__global__ void build_nbr_kernel() {
    int warp = (blockIdx.x * blockDim.x + threadIdx.x) >> 5;
    int lane = threadIdx.x & 31;
    if (warp >= N_TOK) return;
    int i = warp;
    float ei = g_eta[i], pi = g_phi[i];
    int c = 0;
    for (int j0 = 0; j0 < N_TOK; j0 += 32) {
        int j = j0 + lane;
        float de = ei - g_eta[j];
        float dp = pi - g_phi[j];
        dp = dp - 6.283185307179586f * rintf(dp * 0.15915494309189535f);
        float dr2 = de * de + dp * dp;
        bool keep = (dr2 <= 0.04f);
        unsigned m = __ballot_sync(0xffffffffu, keep);
        if (keep) {
            int pos = c + __popc(m & ((1u << lane) - 1u));
            if (pos < CAP) g_nbr[i * CAP + pos] = j;
        }
        c += __popc(m);
    }
    if (lane == 0) g_cnt[i] = (c < CAP) ? c : CAP;
}

// ---------------- LN -> packed planes (2 rows per warp, batched loads) ----------------
__global__ void ln_expand(const float* __restrict__ x,
                          const float* __restrict__ g,
                          const float* __restrict__ b) {
    int warp = (blockIdx.x * blockDim.x + threadIdx.x) >> 5;
    int lane = threadIdx.x & 31;
    int r0 = warp * 2;
    if (r0 >= N_TOK) return;
    const float* row0 = x + (size_t)r0 * 256 + lane * 8;
    const float* row1 = row0 + 256;
    float v0[8], v1[8];
    *(float4*)&v0[0] = *(const float4*)&row0[0];
    *(float4*)&v0[4] = *(const float4*)&row0[4];
    *(float4*)&v1[0] = *(const float4*)&row1[0];
    *(float4*)&v1[4] = *(const float4*)&row1[4];
    float gv[8], bv[8];
    *(float4*)&gv[0] = *(const float4*)&g[lane * 8];
    *(float4*)&gv[4] = *(const float4*)&g[lane * 8 + 4];
    *(float4*)&bv[0] = *(const float4*)&b[lane * 8];
    *(float4*)&bv[4] = *(const float4*)&b[lane * 8 + 4];

    float s0 = 0.f, q0 = 0.f, s1 = 0.f, q1 = 0.f;
#pragma unroll
    for (int j = 0; j < 8; j++) {
        s0 += v0[j]; q0 += v0[j] * v0[j];
        s1 += v1[j]; q1 += v1[j] * v1[j];
    }
#pragma unroll
    for (int off = 16; off; off >>= 1) {
        s0 += __shfl_xor_sync(0xffffffffu, s0, off);
        q0 += __shfl_xor_sync(0xffffffffu, q0, off);
        s1 += __shfl_xor_sync(0xffffffffu, s1, off);
        q1 += __shfl_xor_sync(0xffffffffu, q1, off);
    }
    float m0 = s0 * (1.f / 256.f), m1 = s1 * (1.f / 256.f);
    float i0 = rsqrtf(q0 * (1.f / 256.f) - m0 * m0 + 1e-5f);
    float i1 = rsqrtf(q1 * (1.f / 256.f) - m1 * m1 + 1e-5f);
    __nv_bfloat16 h0[8], l0[8], h1[8], l1[8];
#pragma unroll
    for (int j = 0; j < 8; j++) {
        float y0 = (v0[j] - m0) * i0 * gv[j] + bv[j];
        float y1 = (v1[j] - m1) * i1 * gv[j] + bv[j];
        bf16_split(y0, h0[j], l0[j]);
        bf16_split(y1, h1[j], l1[j]);
    }
    *(uint4*)&g_Aex[(size_t)r0 * 512 + lane * 8]             = *(uint4*)h0;
    *(uint4*)&g_Aex[(size_t)r0 * 512 + 256 + lane * 8]       = *(uint4*)l0;
    *(uint4*)&g_Aex[(size_t)(r0 + 1) * 512 + lane * 8]       = *(uint4*)h1;
    *(uint4*)&g_Aex[(size_t)(r0 + 1) * 512 + 256 + lane * 8] = *(uint4*)l1;
}

// ---------------- plain expand X -> planes ----------------
__global__ void expand_kernel(const float* __restrict__ src) {
    int n = blockIdx.x;
    int t = threadIdx.x;
    float y = src[n * 256 + t];
    __nv_bfloat16 hi, lo;
    bf16_split(y, hi, lo);
    g_Aex[(size_t)n * 512 + t]       = hi;
    g_Aex[(size_t)n * 512 + 256 + t] = lo;
}

// ---------------- streamed 3-stage bf16 GEMM, 64x64 tile ----------------
template<int KDIM, int RELU, int RES, int SPLIT, int EXPAND>
__global__ void __launch_bounds__(256)
fgemm(const __nv_bfloat16* __restrict__ Aex, const __nv_bfloat16* __restrict__ WB,
      const float* __restrict__ bias,
      float* __restrict__ out0, float* __restrict__ out1,
      __nv_bfloat16* __restrict__ Cexp, int Ncols) {
    constexpr int KP    = 3 * KDIM;
    constexpr int NCH   = KP / 64;
    constexpr int ASTR  = 2 * KDIM;
    constexpr int STAGE = 64 * 144 * 2;

    extern __shared__ char smem[];

    int tid  = threadIdx.x;
    int lane = tid & 31;
    int warp = tid >> 5;
    int wm = (warp & 1) * 32;
    int wn = (warp >> 1) * 16;
    int gq = lane >> 2;
    int tq = lane & 3;

    int m0 = blockIdx.y * 64;
    int n0 = blockIdx.x * 64;

    const uint4* Ag = (const uint4*)(Aex + (size_t)m0 * ASTR);
    const uint4* Bg = (const uint4*)(WB  + (size_t)n0 * KP);

    auto issue = [&](int ic, int st) {
        int kglob = ic * 64;
        int plane = kglob / KDIM;
        int k0    = kglob % KDIM;
        int acol8 = ((plane == 1) ? KDIM + k0 : k0) >> 3;
        int bcol8 = kglob >> 3;
        char* sA = smem + st * STAGE;
        char* sB = sA + 64 * 144;
#pragma unroll
        for (int v = 0; v < 2; v++) {
            int e = v * 256 + tid;
            int row = e >> 3, c8 = e & 7;
            cpa16(su32(sA + row * 144 + c8 * 16), Ag + (size_t)row * (ASTR >> 3) + acol8 + c8);
            cpa16(su32(sB + row * 144 + c8 * 16), Bg + (size_t)row * (KP >> 3)   + bcol8 + c8);
        }
        cpa_commit();
    };
    issue(0, 0);
    if (NCH > 1) issue(1, 1);

    float acc[2][2][4];
#pragma unroll
    for (int mt = 0; mt < 2; mt++)
#pragma unroll
        for (int nt = 0; nt < 2; nt++)
#pragma unroll
            for (int r = 0; r < 4; r++) acc[mt][nt][r] = 0.f;

    int lr8 = lane & 7;
    int sel = lane >> 3;
    int aRow = (sel & 1) * 8 + lr8;
    int aCol = (sel >> 1) * 8;
    int bRow = lane & 15;
    int bCol = (lane >> 4) * 8;

    for (int ic = 0; ic < NCH; ic++) {
        if (ic + 2 < NCH) cpa_wait<1>();
        else              cpa_wait<0>();
        __syncthreads();
        if (ic + 2 < NCH) issue(ic + 2, (ic + 2) % 3);

        int st = ic % 3;
        char* sA = smem + st * STAGE;
        char* sB = sA + 64 * 144;
#pragma unroll
        for (int kk = 0; kk < 4; kk++) {
            int kb = kk * 32;
            unsigned a[2][4], b[4];
            ldsm_x4(a[0], su32(sA + (wm + aRow) * 144 + kb + aCol * 2));
            ldsm_x4(a[1], su32(sA + (wm + 16 + aRow) * 144 + kb + aCol * 2));
            ldsm_x4(b,    su32(sB + (wn + bRow) * 144 + kb + bCol * 2));
#pragma unroll
            for (int mt = 0; mt < 2; mt++) {
                mma_bf16(acc[mt][0], a[mt][0], a[mt][1], a[mt][2], a[mt][3], b[0], b[2]);
                mma_bf16(acc[mt][1], a[mt][0], a[mt][1], a[mt][2], a[mt][3], b[1], b[3]);
            }
        }
    }

#pragma unroll
    for (int mt = 0; mt < 2; mt++) {
#pragma unroll
        for (int half = 0; half < 2; half++) {
            int row = m0 + wm + mt * 16 + gq + half * 8;
#pragma unroll
            for (int nt = 0; nt < 2; nt++) {
                int col = n0 + wn + nt * 8 + 2 * tq;
                float v0 = acc[mt][nt][half * 2 + 0] + bias[col];
                float v1 = acc[mt][nt][half * 2 + 1] + bias[col + 1];
                if (RELU) { v0 = fmaxf(v0, 0.f); v1 = fmaxf(v1, 0.f); }
                if (RES) {
                    float2 old = *(float2*)&out0[(size_t)row * Ncols + col];
                    v0 += old.x; v1 += old.y;
                }
                if (EXPAND) {
                    __nv_bfloat16 h0, l0, h1, l1;
                    bf16_split(v0, h0, l0);
                    bf16_split(v1, h1, l1);
                    size_t base = (size_t)row * 2 * Ncols;
                    Cexp[base + col]             = h0;
                    Cexp[base + col + 1]         = h1;
                    Cexp[base + Ncols + col]     = l0;
                    Cexp[base + Ncols + col + 1] = l1;
                } else if (SPLIT) {
                    if (col < 256) *(float2*)&out0[(size_t)row * 256 + col] = make_float2(v0, v1);
                    else           *(float2*)&out1[(size_t)row * 128 + (col - 256)] = make_float2(v0, v1);
                } else {
                    *(float2*)&out0[(size_t)row * Ncols + col] = make_float2(v0, v1);
                }
            }
        }
    }
}

// ---------------- streamed 3-stage bf16 GEMM, 128x64 tile ----------------
// NPLANES=3: full error-compensated (K' = 3K). NPLANES=1: hi-plane only (K' = K).
// B storage stride is always 3K (expanded weights). Output col = col0 + n-rel;
// out0 row stride = ostride.
template<int KDIM, int NPLANES, int RELU, int EXPAND>
__global__ void __launch_bounds__(256)
fgemm128(const __nv_bfloat16* __restrict__ Aex, const __nv_bfloat16* __restrict__ WB,
         const float* __restrict__ bias,
         float* __restrict__ out0, __nv_bfloat16* __restrict__ Cexp,
         int col0, int ostride) {
    constexpr int KP    = 3 * KDIM;             // B row stride (storage)
    constexpr int NCH   = (NPLANES == 1 ? KDIM : 3 * KDIM) / 64;
    constexpr int ASTR  = 2 * KDIM;
    constexpr int STAGE = 192 * 144;

    extern __shared__ char smem[];

    int tid  = threadIdx.x;
    int lane = tid & 31;
    int warp = tid >> 5;
    int wm = (warp >> 1) * 32;
    int wn = (warp & 1)  * 32;
    int gq = lane >> 2;
    int tq = lane & 3;

    int m0 = blockIdx.y * 128;
    int nrel = blockIdx.x * 64;

    const uint4* Ag = (const uint4*)(Aex + (size_t)m0 * ASTR);
    const uint4* Bg = (const uint4*)(WB  + (size_t)nrel * KP);

    auto issue = [&](int ic, int st) {
        int kglob = ic * 64;
        int plane = kglob / KDIM;
        int k0    = kglob % KDIM;
        int acol8 = ((plane == 1) ? KDIM + k0 : k0) >> 3;
        int bcol8 = kglob >> 3;
        char* sA = smem + st * STAGE;
        char* sB = sA + 128 * 144;
#pragma unroll
        for (int v = 0; v < 4; v++) {
            int e = v * 256 + tid;
            int row = e >> 3, c8 = e & 7;
            cpa16(su32(sA + row * 144 + c8 * 16), Ag + (size_t)row * (ASTR >> 3) + acol8 + c8);
        }
#pragma unroll
        for (int v = 0; v < 2; v++) {
            int e = v * 256 + tid;
            int row = e >> 3, c8 = e & 7;
            cpa16(su32(sB + row * 144 + c8 * 16), Bg + (size_t)row * (KP >> 3) + bcol8 + c8);
        }
        cpa_commit();
    };
    issue(0, 0);
    if (NCH > 1) issue(1, 1);

    float acc[2][4][4];
#pragma unroll
    for (int mt = 0; mt < 2; mt++)
#pragma unroll
        for (int nt = 0; nt < 4; nt++)
#pragma unroll
            for (int r = 0; r < 4; r++) acc[mt][nt][r] = 0.f;

    int lr8 = lane & 7;
    int sel = lane >> 3;
    int aRow = (sel & 1) * 8 + lr8;
    int aCol = (sel >> 1) * 8;
    int bRow = lane & 15;
    int bCol = (lane >> 4) * 8;

    for (int ic = 0; ic < NCH; ic++) {
        if (ic + 2 < NCH) cpa_wait<1>();
        else              cpa_wait<0>();
        __syncthreads();
        if (ic + 2 < NCH) issue(ic + 2, (ic + 2) % 3);

        int st = ic % 3;
        char* sA = smem + st * STAGE;
        char* sB = sA + 128 * 144;
#pragma unroll
        for (int kk = 0; kk < 4; kk++) {
            int kb = kk * 32;
            unsigned a[2][4], b[2][4];
            ldsm_x4(a[0], su32(sA + (wm + aRow) * 144 + kb + aCol * 2));
            ldsm_x4(a[1], su32(sA + (wm + 16 + aRow) * 144 + kb + aCol * 2));
            ldsm_x4(b[0], su32(sB + (wn + bRow) * 144 + kb + bCol * 2));
            ldsm_x4(b[1], su32(sB + (wn + 16 + bRow) * 144 + kb + bCol * 2));
#pragma unroll
            for (int mt = 0; mt < 2; mt++)
#pragma unroll
                for (int nt = 0; nt < 4; nt++)
                    mma_bf16(acc[mt][nt], a[mt][0], a[mt][1], a[mt][2], a[mt][3],
                             b[nt >> 1][nt & 1], b[nt >> 1][(nt & 1) + 2]);
        }
    }

#pragma unroll
    for (int mt = 0; mt < 2; mt++) {
#pragma unroll
        for (int half = 0; half < 2; half++) {
            int row = m0 + wm + mt * 16 + gq + half * 8;
#pragma unroll
            for (int nt = 0; nt < 4; nt++) {
                int col = col0 + nrel + wn + nt * 8 + 2 * tq;
                float v0 = acc[mt][nt][half * 2 + 0] + bias[col];
                float v1 = acc[mt][nt][half * 2 + 1] + bias[col + 1];
                if (RELU) { v0 = fmaxf(v0, 0.f); v1 = fmaxf(v1, 0.f); }
                if (EXPAND) {
                    __nv_bfloat16 h0, l0, h1, l1;
                    bf16_split(v0, h0, l0);
                    bf16_split(v1, h1, l1);
                    size_t base = (size_t)row * 2 * ostride;
                    Cexp[base + col]               = h0;
                    Cexp[base + col + 1]           = h1;
                    Cexp[base + ostride + col]     = l0;
                    Cexp[base + ostride + col + 1] = l1;
                } else {
                    *(float2*)&out0[(size_t)row * ostride + col] = make_float2(v0, v1);
                }
            }
        }
    }
}

// ---------------- sparse attention: depth-1 prefetch pipeline ----------------
__global__ void attn_kernel() {
    int warp = (blockIdx.x * blockDim.x + threadIdx.x) >> 5;
    int lane = threadIdx.x & 31;
    int n = warp >> 3;
    int h = warp & 7;
    if (n >= N_TOK) return;
    const float scale = 0.17677669529663687f;   // 1/sqrt(32)
    float q = g_QKV[n * 768 + h * 32 + lane];
    int c = g_cnt[n];
    const int* nb = g_nbr + n * CAP;

    float m = -1e30f, s = 0.f, o = 0.f;
    int j = nb[0];
    float kv = g_QKV[j * 768 + 256 + h * 32 + lane];
    float vv = g_QKV[j * 768 + 512 + h * 32 + lane];
    for (int t = 0; t < c; t++) {
        float kv2 = 0.f, vv2 = 0.f;
        if (t + 1 < c) {                        // prefetch next neighbor
            int j2 = nb[t + 1];
            kv2 = g_QKV[j2 * 768 + 256 + h * 32 + lane];
            vv2 = g_QKV[j2 * 768 + 512 + h * 32 + lane];
        }
        float prod = q * kv;
#pragma unroll
        for (int off = 16; off; off >>= 1) prod += __shfl_xor_sync(0xffffffffu, prod, off);
        float sc = prod * scale;
        float mn = fmaxf(m, sc);
        float corr = __expf(m - mn);
        float p = __expf(sc - mn);
        s = s * corr + p;
        o = o * corr + p * vv;
        m = mn;
        kv = kv2; vv = vv2;
    }
    float y = o / s;
    __nv_bfloat16 hi, lo;
    bf16_split(y, hi, lo);
    int col = h * 32 + lane;
    g_Aex[(size_t)n * 512 + col]       = hi;
    g_Aex[(size_t)n * 512 + 256 + col] = lo;
}

// ---------------- finals: coords (24-col gemm) + beta head ----------------
__global__ void finals_kernel(const float* __restrict__ Wl2, const float* __restrict__ bl2,
                              const float* __restrict__ Wb2, const float* __restrict__ bb2,
                              float* __restrict__ out) {
    if (blockIdx.x < 192) {
        int idx = blockIdx.x * 256 + threadIdx.x;
        int row = idx / 24;
        int o   = idx % 24;
        const float* a = g_T1 + (size_t)row * 256;
        const float* w = Wl2 + (size_t)o * 256;
        float s = 0.f;
#pragma unroll 8
        for (int k = 0; k < 256; k++) s += a[k] * w[k];
        out[N_TOK + (size_t)row * 24 + o] = s + bl2[o];
    } else {
        int b2 = blockIdx.x - 192;
        int warp = b2 * 8 + (threadIdx.x >> 5);
        int lane = threadIdx.x & 31;
        if (warp >= N_TOK) return;
        float s = 0.f;
#pragma unroll
        for (int k = lane; k < 128; k += 32) s += g_T2[warp * 128 + k] * Wb2[k];
#pragma unroll
        for (int off = 16; off; off >>= 1) s += __shfl_xor_sync(0xffffffffu, s, off);
        if (lane == 0) {
            float z = s + bb2[0];
            float b = 1.f / (1.f + expf(-z));
            b = fminf(fmaxf(b, 1e-6f), 1.f - 1e-6f);
            out[warp] = b;
        }
    }
}

extern "C" void kernel_launch(void* const* d_in, const int* in_sizes, int n_in,
                              void* d_out, int out_size) {
    const float* x_raw = (const float*)d_in[0];
    const float* Win  = (const float*)d_in[2];
    const float* b_in = (const float*)d_in[3];
    const float* Wqkv = (const float*)d_in[4];
    const float* bqkv = (const float*)d_in[5];
    const float* Wo   = (const float*)d_in[6];
    const float* bo   = (const float*)d_in[7];
    const float* W1   = (const float*)d_in[8];
    const float* b1   = (const float*)d_in[9];
    const float* W2   = (const float*)d_in[10];
    const float* b2   = (const float*)d_in[11];
    const float* g1   = (const float*)d_in[12];
    const float* be1  = (const float*)d_in[13];
    const float* g2   = (const float*)d_in[14];
    const float* be2  = (const float*)d_in[15];
    const float* Wl1  = (const float*)d_in[16];
    const float* bl1  = (const float*)d_in[17];
    const float* Wl2  = (const float*)d_in[18];
    const float* bl2  = (const float*)d_in[19];
    const float* Wb1  = (const float*)d_in[20];
    const float* bb1  = (const float*)d_in[21];
    const float* Wb2  = (const float*)d_in[22];
    const float* bb2  = (const float*)d_in[23];
    float* out = (float*)d_out;

    float *pX, *pQKV, *pT1, *pT2, *pbhd;
    cudaGetSymbolAddress((void**)&pX,   g_X);
    cudaGetSymbolAddress((void**)&pQKV, g_QKV);
    cudaGetSymbolAddress((void**)&pT1,  g_T1);
    cudaGetSymbolAddress((void**)&pT2,  g_T2);
    cudaGetSymbolAddress((void**)&pbhd, g_bhd);
    __nv_bfloat16 *pAex, *pFFex, *pWBqkv, *pWBo, *pWB1, *pWB2, *pWBhd;
    cudaGetSymbolAddress((void**)&pAex,   g_Aex);
    cudaGetSymbolAddress((void**)&pFFex,  g_FFex);
    cudaGetSymbolAddress((void**)&pWBqkv, g_WBqkv);
    cudaGetSymbolAddress((void**)&pWBo,   g_WBo);
    cudaGetSymbolAddress((void**)&pWB1,   g_WB1);
    cudaGetSymbolAddress((void**)&pWB2,   g_WB2);
    cudaGetSymbolAddress((void**)&pWBhd,  g_WBhd);

    const int SMEM3  = 3 * 64 * 144 * 2;    // 55296
    const int SMEM3B = 3 * 192 * 144;       // 82944
    cudaFuncSetAttribute(fgemm<256,0,1,0,0>,  cudaFuncAttributeMaxDynamicSharedMemorySize, SMEM3);
    cudaFuncSetAttribute(fgemm<512,0,1,0,0>,  cudaFuncAttributeMaxDynamicSharedMemorySize, SMEM3);
    cudaFuncSetAttribute(fgemm<256,1,0,1,0>,  cudaFuncAttributeMaxDynamicSharedMemorySize, SMEM3);
    cudaFuncSetAttribute(fgemm128<256,1,0,0>, cudaFuncAttributeMaxDynamicSharedMemorySize, SMEM3B);
    cudaFuncSetAttribute(fgemm128<256,3,0,0>, cudaFuncAttributeMaxDynamicSharedMemorySize, SMEM3B);
    cudaFuncSetAttribute(fgemm128<256,3,1,1>, cudaFuncAttributeMaxDynamicSharedMemorySize, SMEM3B);

    convw_all<<<2048, 256>>>(Wqkv, Wo, W1, W2, Wl1, Wb1, bl1, bb1);
    embed_kernel<<<N_TOK, HDIM>>>(x_raw, Win, b_in);
    build_nbr_kernel<<<N_TOK / 8, 256>>>();

    for (int l = 0; l < NLAYER; l++) {
        const __nv_bfloat16* WBqkv_l = pWBqkv + (size_t)l * 768 * 768;
        const __nv_bfloat16* WBo_l   = pWBo   + (size_t)l * 256 * 768;
        const __nv_bfloat16* WB1_l   = pWB1   + (size_t)l * 512 * 768;
        const __nv_bfloat16* WB2_l   = pWB2   + (size_t)l * 256 * 1536;

        ln_expand<<<N_TOK / 16, 256>>>(pX, g1 + l * 256, be1 + l * 256);
        // Q,K at 1x bf16 (scores only; error analysis in header note)
        fgemm128<256,1,0,0><<<dim3(8, 16), 256, SMEM3B>>>(
            pAex, WBqkv_l, bqkv + l * 768, pQKV, nullptr, 0, 768);
        // V at full 3x compensation
        fgemm128<256,3,0,0><<<dim3(4, 16), 256, SMEM3B>>>(
            pAex, WBqkv_l + (size_t)512 * 768, bqkv + l * 768, pQKV, nullptr, 512, 768);
        attn_kernel<<<(N_TOK * 8 * 32) / 256, 256>>>();
        fgemm<256,0,1,0,0><<<dim3(4, 32), 256, SMEM3>>>(
            pAex, WBo_l, bo + l * 256, pX, nullptr, nullptr, 256);
        ln_expand<<<N_TOK / 16, 256>>>(pX, g2 + l * 256, be2 + l * 256);
        fgemm128<256,3,1,1><<<dim3(8, 16), 256, SMEM3B>>>(
            pAex, WB1_l, b1 + l * 512, nullptr, pFFex, 0, 512);
        fgemm<512,0,1,0,0><<<dim3(4, 32), 256, SMEM3>>>(
            pFFex, WB2_l, b2 + l * 256, pX, nullptr, nullptr, 256);
    }

    // heads
    expand_kernel<<<N_TOK, HDIM>>>(pX);
    fgemm<256,1,0,1,0><<<dim3(6, 32), 256, SMEM3>>>(
        pAex, pWBhd, pbhd, pT1, pT2, nullptr, 384);
    finals_kernel<<<448, 256>>>(Wl2, bl2, Wb2, bb2, out);
}